// round 6
// baseline (speedup 1.0000x reference)
#include <cuda_runtime.h>
#include <cuda_bf16.h>
#include <cstdint>
#include <math.h>

#define SEQ   1024
#define DIM   1024
#define NHEAD 16
#define HDIM  64
#define BATCH 4
#define NTOK  (BATCH*SEQ)
#define NBH   (BATCH*NHEAD)

// ---------------- scratch (allocation-free rule) ----------------
__device__ __nv_bfloat16 g_xh[NTOK*DIM],  g_xl[NTOK*DIM];
__device__ __nv_bfloat16 g_wh[4*DIM*DIM], g_wl[4*DIM*DIM];
__device__ __nv_bfloat16 g_qh[NBH*SEQ*HDIM], g_ql[NBH*SEQ*HDIM];
__device__ __nv_bfloat16 g_kh[NBH*SEQ*HDIM], g_kl[NBH*SEQ*HDIM];
__device__ __nv_bfloat16 g_vh[NBH*SEQ*HDIM], g_vl[NBH*SEQ*HDIM];
__device__ __nv_bfloat16 g_wah[NTOK*DIM], g_wal[NTOK*DIM];

// ---------------- PTX helpers ----------------
__device__ __forceinline__ uint32_t smem_u32(const void* p) {
    uint32_t a;
    asm("{ .reg .u64 t; cvta.to.shared.u64 t, %1; cvt.u32.u64 %0, t; }" : "=r"(a) : "l"(p));
    return a;
}
#define CPA16(d, s)  asm volatile("cp.async.cg.shared.global [%0], [%1], 16;" :: "r"(d), "l"(s) : "memory")
#define CPA_COMMIT() asm volatile("cp.async.commit_group;" ::: "memory")
#define CPA_WAIT(n)  asm volatile("cp.async.wait_group %0;" :: "n"(n) : "memory")

#define LDSM_X4(r, addr) \
    asm volatile("ldmatrix.sync.aligned.m8n8.x4.shared.b16 {%0,%1,%2,%3}, [%4];" \
        : "=r"((r)[0]), "=r"((r)[1]), "=r"((r)[2]), "=r"((r)[3]) : "r"(addr))
#define LDSM_X4T(r, addr) \
    asm volatile("ldmatrix.sync.aligned.m8n8.x4.trans.shared.b16 {%0,%1,%2,%3}, [%4];" \
        : "=r"((r)[0]), "=r"((r)[1]), "=r"((r)[2]), "=r"((r)[3]) : "r"(addr))

#define MMA16816(d, a, b0, b1) \
    asm volatile("mma.sync.aligned.m16n8k16.row.col.f32.bf16.bf16.f32 " \
        "{%0,%1,%2,%3}, {%4,%5,%6,%7}, {%8,%9}, {%0,%1,%2,%3};" \
        : "+f"((d)[0]), "+f"((d)[1]), "+f"((d)[2]), "+f"((d)[3]) \
        : "r"((a)[0]), "r"((a)[1]), "r"((a)[2]), "r"((a)[3]), "r"(b0), "r"(b1))

__device__ __forceinline__ uint32_t sw128(uint32_t boff) {
    return boff ^ ((boff >> 3) & 0x70);
}
__device__ __forceinline__ void split_store(__nv_bfloat16* __restrict__ hi,
                                            __nv_bfloat16* __restrict__ lo,
                                            long long off, float v0, float v1) {
    __nv_bfloat162 H, L;
    H.x = __float2bfloat16(v0); H.y = __float2bfloat16(v1);
    L.x = __float2bfloat16(v0 - __bfloat162float(H.x));
    L.y = __float2bfloat16(v1 - __bfloat162float(H.y));
    *(__nv_bfloat162*)(hi + off) = H;
    *(__nv_bfloat162*)(lo + off) = L;
}
__device__ __forceinline__ void pack_split(float a, float b, uint32_t& h, uint32_t& l) {
    __nv_bfloat162 H, L;
    H.x = __float2bfloat16(a); H.y = __float2bfloat16(b);
    L.x = __float2bfloat16(a - __bfloat162float(H.x));
    L.y = __float2bfloat16(b - __bfloat162float(H.y));
    h = *(uint32_t*)&H; l = *(uint32_t*)&L;
}

struct GParams {
    const __nv_bfloat16* Bh[3];
    const __nv_bfloat16* Bl[3];
    const float*         bias[3];
    __nv_bfloat16*       Ch[3];
    __nv_bfloat16*       Cl[3];
    float*               Cf;
};

// ---------------------------------------------------------------------------
// mma.sync bf16 GEMM, 3-term split compensation per K-chunk (hi/lo loaded once).
// C[128 x BN], 256 thr = 8 warps (4m x 2n), 3-stage cp.async pipeline.
// MMA emission is term-major: 4 independent accumulators between reuse.
// EPI 0: fp32 out (ldc);  EPI 1: split bf16 scatter [B,H,S,Hd]
// ---------------------------------------------------------------------------
template<int BN, int EPI>
__global__ void __launch_bounds__(256, 1)
tc_gemm(const __nv_bfloat16* __restrict__ Ahi, const __nv_bfloat16* __restrict__ Alo,
        GParams gpar, int K, int lda, int ldb, int ldc)
{
    extern __shared__ char dsm[];
    constexpr int NTW    = BN / 16;
    constexpr int ABYTES = 128 * 128;
    constexpr int BBYTES = BN * 128;
    constexpr int STG    = 2 * ABYTES + 2 * BBYTES;

    const int tid    = threadIdx.x;
    const int lane   = tid & 31;
    const int wid    = tid >> 5;
    const int warp_m = wid & 3;
    const int warp_n = wid >> 2;
    const int row0   = blockIdx.y * 128;
    const int col0   = blockIdx.x * BN;
    const int z      = blockIdx.z;

    const __nv_bfloat16* __restrict__ Bh = gpar.Bh[z];
    const __nv_bfloat16* __restrict__ Bl = gpar.Bl[z];
    const float* __restrict__ bias       = gpar.bias[z];

    const uint32_t dyn0 = smem_u32(dsm);
    const uint32_t dyn  = (dyn0 + 1023) & ~1023u;

    const int nch = K / 64;

    auto load_chunk = [&](int c) {
        const uint32_t s = dyn + (c % 3) * STG;
        const int koff = c * 64;
        #pragma unroll
        for (int i = 0; i < 4; i++) {
            int lin = tid + i * 256;
            int r = lin >> 3, sg = lin & 7;
            uint32_t sw = sw128((uint32_t)(r * 128 + sg * 16));
            long long go = (long long)(row0 + r) * lda + koff + sg * 8;
            CPA16(s + sw,          (const void*)(Ahi + go));
            CPA16(s + ABYTES + sw, (const void*)(Alo + go));
        }
        #pragma unroll
        for (int i = 0; i < BN / 32; i++) {
            int lin = tid + i * 256;
            int r = lin >> 3, sg = lin & 7;
            uint32_t sw = sw128((uint32_t)(r * 128 + sg * 16));
            long long go = (long long)(col0 + r) * ldb + koff + sg * 8;
            CPA16(s + 2 * ABYTES + sw,          (const void*)(Bh + go));
            CPA16(s + 2 * ABYTES + BBYTES + sw, (const void*)(Bl + go));
        }
        CPA_COMMIT();
    };

    float acc[2][NTW][4];
    #pragma unroll
    for (int i = 0; i < 2; i++)
        #pragma unroll
        for (int j = 0; j < NTW; j++)
            #pragma unroll
            for (int q = 0; q < 4; q++) acc[i][j][q] = 0.f;

    load_chunk(0);
    load_chunk(1);

    for (int c = 0; c < nch; c++) {
        if (c + 2 < nch)      { load_chunk(c + 2); CPA_WAIT(2); }
        else if (c + 1 < nch) { CPA_WAIT(1); }
        else                  { CPA_WAIT(0); }
        __syncthreads();

        const uint32_t ah_ = dyn + (c % 3) * STG;
        const uint32_t al_ = ah_ + ABYTES;
        const uint32_t bh_ = ah_ + 2 * ABYTES;
        const uint32_t bl_ = bh_ + BBYTES;

        #pragma unroll
        for (int ks = 0; ks < 4; ks++) {
            uint32_t aH[2][4], aL[2][4];
            #pragma unroll
            for (int im = 0; im < 2; im++) {
                int r = warp_m * 32 + im * 16 + (lane & 15);
                uint32_t boff = (uint32_t)(r * 128 + ks * 32 + (lane >> 4) * 16);
                LDSM_X4(aH[im], ah_ + sw128(boff));
                LDSM_X4(aL[im], al_ + sw128(boff));
            }
            #pragma unroll
            for (int ip = 0; ip < NTW / 2; ip++) {
                uint32_t bH[4], bL[4];
                const int q = lane >> 3, rr = lane & 7;
                int nr = warp_n * (BN / 2) + ip * 16 + ((q >> 1) << 3) + rr;
                uint32_t boff = (uint32_t)(nr * 128 + (ks * 16 + (q & 1) * 8) * 2);
                LDSM_X4(bH, bh_ + sw128(boff));
                LDSM_X4(bL, bl_ + sw128(boff));
                // term-major emission: reuse distance 4
                MMA16816(acc[0][2 * ip],     aH[0], bH[0], bH[1]);
                MMA16816(acc[0][2 * ip + 1], aH[0], bH[2], bH[3]);
                MMA16816(acc[1][2 * ip],     aH[1], bH[0], bH[1]);
                MMA16816(acc[1][2 * ip + 1], aH[1], bH[2], bH[3]);
                MMA16816(acc[0][2 * ip],     aL[0], bH[0], bH[1]);
                MMA16816(acc[0][2 * ip + 1], aL[0], bH[2], bH[3]);
                MMA16816(acc[1][2 * ip],     aL[1], bH[0], bH[1]);
                MMA16816(acc[1][2 * ip + 1], aL[1], bH[2], bH[3]);
                MMA16816(acc[0][2 * ip],     aH[0], bL[0], bL[1]);
                MMA16816(acc[0][2 * ip + 1], aH[0], bL[2], bL[3]);
                MMA16816(acc[1][2 * ip],     aH[1], bL[0], bL[1]);
                MMA16816(acc[1][2 * ip + 1], aH[1], bL[2], bL[3]);
            }
        }
        __syncthreads();
    }

    const int g = lane >> 2, t = lane & 3;
    #pragma unroll
    for (int im = 0; im < 2; im++) {
        #pragma unroll
        for (int in = 0; in < NTW; in++) {
            const float* ac = acc[im][in];
            const int n0 = col0 + warp_n * (BN / 2) + in * 8 + t * 2;
            #pragma unroll
            for (int half = 0; half < 2; half++) {
                const int m = row0 + warp_m * 32 + im * 16 + g + half * 8;
                float v0 = ac[half * 2]     + bias[n0];
                float v1 = ac[half * 2 + 1] + bias[n0 + 1];
                if (EPI == 0) {
                    *(float2*)(gpar.Cf + (long long)m * ldc + n0) = make_float2(v0, v1);
                } else {
                    int b = m >> 10, s = m & 1023, h = n0 >> 6, d = n0 & 63;
                    long long off = ((((long long)(b * NHEAD + h) << 10) + s) * HDIM) + d;
                    split_store(gpar.Ch[z], gpar.Cl[z], off, v0, v1);
                }
            }
        }
    }
}

// ---------------------------------------------------------------------------
// Fused flash attention, 3-stage KV pipeline, term-major MMA emission
// (K-groups and d-groups processed in pairs -> 4 independent accumulators).
// ---------------------------------------------------------------------------
__global__ void __launch_bounds__(256, 1)
flash_attn(const __nv_bfloat16* __restrict__ qh, const __nv_bfloat16* __restrict__ ql,
           const __nv_bfloat16* __restrict__ kh, const __nv_bfloat16* __restrict__ kl,
           const __nv_bfloat16* __restrict__ vh, const __nv_bfloat16* __restrict__ vl,
           __nv_bfloat16* __restrict__ wah, __nv_bfloat16* __restrict__ wal)
{
    extern __shared__ char dsm[];
    const int tid  = threadIdx.x;
    const int lane = tid & 31;
    const int wid  = tid >> 5;
    const int z    = blockIdx.x;
    const int qrow0 = blockIdx.y * 128;

    const uint32_t dyn0 = smem_u32(dsm);
    const uint32_t dyn  = (dyn0 + 1023) & ~1023u;
    const uint32_t sQh = dyn, sQl = dyn + 16384;
    const uint32_t kvb = dyn + 32768;

    const long long zoff = (long long)z * SEQ * HDIM;
    const __nv_bfloat16* Qh = qh + zoff;
    const __nv_bfloat16* Ql = ql + zoff;
    const __nv_bfloat16* Kh = kh + zoff;
    const __nv_bfloat16* Kl = kl + zoff;
    const __nv_bfloat16* Vh = vh + zoff;
    const __nv_bfloat16* Vl = vl + zoff;

    #pragma unroll
    for (int i = 0; i < 4; i++) {
        int lin = tid + i * 256;
        int r = lin >> 3, sg = lin & 7;
        uint32_t sw = sw128((uint32_t)(r * 128 + sg * 16));
        CPA16(sQh + sw, (const void*)(Qh + (long long)(qrow0 + r) * HDIM + sg * 8));
        CPA16(sQl + sw, (const void*)(Ql + (long long)(qrow0 + r) * HDIM + sg * 8));
    }
    CPA_COMMIT();

    auto load_kv = [&](int c) {
        uint32_t b = kvb + (c % 3) * 32768;
        int kv0 = c * 64;
        #pragma unroll
        for (int i = 0; i < 2; i++) {
            int lin = tid + i * 256;
            int r = lin >> 3, sg = lin & 7;
            uint32_t sw = sw128((uint32_t)(r * 128 + sg * 16));
            long long go = (long long)(kv0 + r) * HDIM + sg * 8;
            CPA16(b +         sw, (const void*)(Kh + go));
            CPA16(b + 8192  + sw, (const void*)(Kl + go));
            CPA16(b + 16384 + sw, (const void*)(Vh + go));
            CPA16(b + 24576 + sw, (const void*)(Vl + go));
        }
        CPA_COMMIT();
    };
    load_kv(0);
    load_kv(1);

    const int g = lane >> 2, t = lane & 3;
    float O[8][4];
    #pragma unroll
    for (int j = 0; j < 8; j++)
        #pragma unroll
        for (int q = 0; q < 4; q++) O[j][q] = 0.f;
    float m0 = -1e30f, m1 = -1e30f, l0 = 0.f, l1 = 0.f;

    const int NKV = SEQ / 64;
    for (int c = 0; c < NKV; c++) {
        if (c + 2 < NKV)      { load_kv(c + 2); CPA_WAIT(2); }
        else if (c + 1 < NKV) { CPA_WAIT(1); }
        else                  { CPA_WAIT(0); }
        __syncthreads();

        const uint32_t base = kvb + (c % 3) * 32768;
        const uint32_t bKh = base, bKl = base + 8192;
        const uint32_t bVh = base + 16384, bVl = base + 24576;

        float S[8][4];
        #pragma unroll
        for (int j = 0; j < 8; j++)
            #pragma unroll
            for (int q = 0; q < 4; q++) S[j][q] = 0.f;

        // ---- S = QK^T (3-term), group-paired, term-major ----
        #pragma unroll
        for (int ks = 0; ks < 4; ks++) {
            uint32_t aH[4], aL[4];
            {
                int r = wid * 16 + (lane & 15);
                uint32_t boff = (uint32_t)(r * 128 + ks * 32 + (lane >> 4) * 16);
                LDSM_X4(aH, sQh + sw128(boff));
                LDSM_X4(aL, sQl + sw128(boff));
            }
            #pragma unroll
            for (int gp = 0; gp < 2; gp++) {
                uint32_t bH0[4], bL0[4], bH1[4], bL1[4];
                const int q = lane >> 3, rr = lane & 7;
                int nr0 = (2 * gp)     * 16 + ((q >> 1) << 3) + rr;
                int nr1 = (2 * gp + 1) * 16 + ((q >> 1) << 3) + rr;
                uint32_t bo0 = (uint32_t)(nr0 * 128 + (ks * 16 + (q & 1) * 8) * 2);
                uint32_t bo1 = (uint32_t)(nr1 * 128 + (ks * 16 + (q & 1) * 8) * 2);
                LDSM_X4(bH0, bKh + sw128(bo0));
                LDSM_X4(bL0, bKl + sw128(bo0));
                LDSM_X4(bH1, bKh + sw128(bo1));
                LDSM_X4(bL1, bKl + sw128(bo1));
                float* S0 = S[4 * gp];     float* S1 = S[4 * gp + 1];
                float* S2 = S[4 * gp + 2]; float* S3 = S[4 * gp + 3];
                MMA16816(S0, aH, bH0[0], bH0[1]);
                MMA16816(S1, aH, bH0[2], bH0[3]);
                MMA16816(S2, aH, bH1[0], bH1[1]);
                MMA16816(S3, aH, bH1[2], bH1[3]);
                MMA16816(S0, aL, bH0[0], bH0[1]);
                MMA16816(S1, aL, bH0[2], bH0[3]);
                MMA16816(S2, aL, bH1[0], bH1[1]);
                MMA16816(S3, aL, bH1[2], bH1[3]);
                MMA16816(S0, aH, bL0[0], bL0[1]);
                MMA16816(S1, aH, bL0[2], bL0[3]);
                MMA16816(S2, aH, bL1[0], bL1[1]);
                MMA16816(S3, aH, bL1[2], bL1[3]);
            }
        }

        // ---- online softmax ----
        float mx0 = -1e30f, mx1 = -1e30f;
        #pragma unroll
        for (int j = 0; j < 8; j++) {
            S[j][0] *= 0.125f; S[j][1] *= 0.125f; S[j][2] *= 0.125f; S[j][3] *= 0.125f;
            mx0 = fmaxf(mx0, fmaxf(S[j][0], S[j][1]));
            mx1 = fmaxf(mx1, fmaxf(S[j][2], S[j][3]));
        }
        mx0 = fmaxf(mx0, __shfl_xor_sync(0xffffffffu, mx0, 1));
        mx0 = fmaxf(mx0, __shfl_xor_sync(0xffffffffu, mx0, 2));
        mx1 = fmaxf(mx1, __shfl_xor_sync(0xffffffffu, mx1, 1));
        mx1 = fmaxf(mx1, __shfl_xor_sync(0xffffffffu, mx1, 2));
        float nm0 = fmaxf(m0, mx0), nm1 = fmaxf(m1, mx1);
        float c0 = __expf(m0 - nm0), c1 = __expf(m1 - nm1);
        m0 = nm0; m1 = nm1;

        uint32_t PH[4][4], PL[4][4];
        float s0 = 0.f, s1 = 0.f;
        #pragma unroll
        for (int ck = 0; ck < 4; ck++) {
            float p00 = __expf(S[2 * ck][0] - nm0),   p01 = __expf(S[2 * ck][1] - nm0);
            float p02 = __expf(S[2 * ck][2] - nm1),   p03 = __expf(S[2 * ck][3] - nm1);
            float p10 = __expf(S[2 * ck + 1][0] - nm0), p11 = __expf(S[2 * ck + 1][1] - nm0);
            float p12 = __expf(S[2 * ck + 1][2] - nm1), p13 = __expf(S[2 * ck + 1][3] - nm1);
            s0 += p00 + p01 + p10 + p11;
            s1 += p02 + p03 + p12 + p13;
            pack_split(p00, p01, PH[ck][0], PL[ck][0]);
            pack_split(p02, p03, PH[ck][1], PL[ck][1]);
            pack_split(p10, p11, PH[ck][2], PL[ck][2]);
            pack_split(p12, p13, PH[ck][3], PL[ck][3]);
        }
        l0 = l0 * c0 + s0;
        l1 = l1 * c1 + s1;
        #pragma unroll
        for (int j = 0; j < 8; j++) {
            O[j][0] *= c0; O[j][1] *= c0; O[j][2] *= c1; O[j][3] *= c1;
        }

        // ---- O += P V (3-term), d-group-paired, term-major ----
        #pragma unroll
        for (int ck = 0; ck < 4; ck++) {
            #pragma unroll
            for (int dp = 0; dp < 2; dp++) {
                uint32_t bH0[4], bL0[4], bH1[4], bL1[4];
                const int q = lane >> 3, rr = lane & 7;
                int kr = ck * 16 + (q & 1) * 8 + rr;
                int nc0 = (2 * dp)     * 16 + ((q >> 1) << 3);
                int nc1 = (2 * dp + 1) * 16 + ((q >> 1) << 3);
                uint32_t bo0 = (uint32_t)(kr * 128 + nc0 * 2);
                uint32_t bo1 = (uint32_t)(kr * 128 + nc1 * 2);
                LDSM_X4T(bH0, bVh + sw128(bo0));
                LDSM_X4T(bL0, bVl + sw128(bo0));
                LDSM_X4T(bH1, bVh + sw128(bo1));
                LDSM_X4T(bL1, bVl + sw128(bo1));
                float* O0 = O[4 * dp];     float* O1 = O[4 * dp + 1];
                float* O2 = O[4 * dp + 2]; float* O3 = O[4 * dp + 3];
                MMA16816(O0, PH[ck], bH0[0], bH0[1]);
                MMA16816(O1, PH[ck], bH0[2], bH0[3]);
                MMA16816(O2, PH[ck], bH1[0], bH1[1]);
                MMA16816(O3, PH[ck], bH1[2], bH1[3]);
                MMA16816(O0, PL[ck], bH0[0], bH0[1]);
                MMA16816(O1, PL[ck], bH0[2], bH0[3]);
                MMA16816(O2, PL[ck], bH1[0], bH1[1]);
                MMA16816(O3, PL[ck], bH1[2], bH1[3]);
                MMA16816(O0, PH[ck], bL0[0], bL0[1]);
                MMA16816(O1, PH[ck], bL0[2], bL0[3]);
                MMA16816(O2, PH[ck], bL1[0], bL1[1]);
                MMA16816(O3, PH[ck], bL1[2], bL1[3]);
            }
        }
        __syncthreads();
    }

    l0 += __shfl_xor_sync(0xffffffffu, l0, 1);
    l0 += __shfl_xor_sync(0xffffffffu, l0, 2);
    l1 += __shfl_xor_sync(0xffffffffu, l1, 1);
    l1 += __shfl_xor_sync(0xffffffffu, l1, 2);
    float inv0 = 1.f / l0, inv1 = 1.f / l1;

    const int b = z >> 4, h = z & 15;
    const int r0 = qrow0 + wid * 16 + g;
    #pragma unroll
    for (int j = 0; j < 8; j++) {
        int d = j * 8 + t * 2;
        long long off0 = (((long long)(b << 10) + r0) << 10) + h * HDIM + d;
        long long off1 = (((long long)(b << 10) + r0 + 8) << 10) + h * HDIM + d;
        split_store(wah, wal, off0, O[j][0] * inv0, O[j][1] * inv0);
        split_store(wah, wal, off1, O[j][2] * inv1, O[j][3] * inv1);
    }
}

// ---------------------------------------------------------------------------
struct SplitP {
    const float* in[5];
    __nv_bfloat16* hi[5];
    __nv_bfloat16* lo[5];
};

__global__ void __launch_bounds__(256)
split_all(SplitP p)
{
    int idx = blockIdx.x * 256 + threadIdx.x;
    int r, local;
    if (idx < (1 << 20)) { r = 0; local = idx; }
    else {
        int t2 = idx - (1 << 20);
        r = 1 + (t2 >> 18);
        local = t2 & ((1 << 18) - 1);
    }
    float4 v = ((const float4*)p.in[r])[local];
    __nv_bfloat16 h0 = __float2bfloat16(v.x), h1 = __float2bfloat16(v.y);
    __nv_bfloat16 h2 = __float2bfloat16(v.z), h3 = __float2bfloat16(v.w);
    __nv_bfloat162 H0; H0.x = h0; H0.y = h1;
    __nv_bfloat162 H1; H1.x = h2; H1.y = h3;
    __nv_bfloat162 L0, L1;
    L0.x = __float2bfloat16(v.x - __bfloat162float(h0));
    L0.y = __float2bfloat16(v.y - __bfloat162float(h1));
    L1.x = __float2bfloat16(v.z - __bfloat162float(h2));
    L1.y = __float2bfloat16(v.w - __bfloat162float(h3));
    ((__nv_bfloat162*)p.hi[r])[2 * local]     = H0;
    ((__nv_bfloat162*)p.hi[r])[2 * local + 1] = H1;
    ((__nv_bfloat162*)p.lo[r])[2 * local]     = L0;
    ((__nv_bfloat162*)p.lo[r])[2 * local + 1] = L1;
}

// ---------------------------------------------------------------------------
extern "C" void kernel_launch(void* const* d_in, const int* in_sizes, int n_in,
                              void* d_out, int out_size)
{
    (void)in_sizes; (void)n_in; (void)out_size;
    const float* x  = (const float*)d_in[0];
    const float* Wq = (const float*)d_in[1];
    const float* bq = (const float*)d_in[2];
    const float* Wk = (const float*)d_in[3];
    const float* bk = (const float*)d_in[4];
    const float* Wv = (const float*)d_in[5];
    const float* bv = (const float*)d_in[6];
    const float* Wp = (const float*)d_in[7];
    const float* bp = (const float*)d_in[8];
    float* out = (float*)d_out;

    __nv_bfloat16 *xh, *xl, *wh, *wl, *qh, *ql, *kh, *kl, *vh, *vl, *wah, *wal;
    cudaGetSymbolAddress((void**)&xh,  g_xh);
    cudaGetSymbolAddress((void**)&xl,  g_xl);
    cudaGetSymbolAddress((void**)&wh,  g_wh);
    cudaGetSymbolAddress((void**)&wl,  g_wl);
    cudaGetSymbolAddress((void**)&qh,  g_qh);
    cudaGetSymbolAddress((void**)&ql,  g_ql);
    cudaGetSymbolAddress((void**)&kh,  g_kh);
    cudaGetSymbolAddress((void**)&kl,  g_kl);
    cudaGetSymbolAddress((void**)&vh,  g_vh);
    cudaGetSymbolAddress((void**)&vl,  g_vl);
    cudaGetSymbolAddress((void**)&wah, g_wah);
    cudaGetSymbolAddress((void**)&wal, g_wal);

    const int SM128 = 3 * 65536 + 1024;
    const int SMFA  = 32768 + 3 * 32768 + 1024;
    cudaFuncSetAttribute(tc_gemm<128, 1>, cudaFuncAttributeMaxDynamicSharedMemorySize, SM128);
    cudaFuncSetAttribute(tc_gemm<128, 0>, cudaFuncAttributeMaxDynamicSharedMemorySize, SM128);
    cudaFuncSetAttribute(flash_attn,      cudaFuncAttributeMaxDynamicSharedMemorySize, SMFA);

    SplitP sp;
    sp.in[0] = x;  sp.hi[0] = xh;                  sp.lo[0] = xl;
    sp.in[1] = Wq; sp.hi[1] = wh + 0 * DIM * DIM;  sp.lo[1] = wl + 0 * DIM * DIM;
    sp.in[2] = Wk; sp.hi[2] = wh + 1 * DIM * DIM;  sp.lo[2] = wl + 1 * DIM * DIM;
    sp.in[3] = Wv; sp.hi[3] = wh + 2 * DIM * DIM;  sp.lo[3] = wl + 2 * DIM * DIM;
    sp.in[4] = Wp; sp.hi[4] = wh + 3 * DIM * DIM;  sp.lo[4] = wl + 3 * DIM * DIM;
    split_all<<<(1 << 20) / 256 + 4 * ((1 << 18) / 256), 256>>>(sp);

    dim3 blk(256);

    GParams gq = {};
    gq.Bh[0] = wh + 0 * DIM * DIM; gq.Bl[0] = wl + 0 * DIM * DIM; gq.bias[0] = bq;
    gq.Bh[1] = wh + 1 * DIM * DIM; gq.Bl[1] = wl + 1 * DIM * DIM; gq.bias[1] = bk;
    gq.Bh[2] = wh + 2 * DIM * DIM; gq.Bl[2] = wl + 2 * DIM * DIM; gq.bias[2] = bv;
    gq.Ch[0] = qh; gq.Cl[0] = ql;
    gq.Ch[1] = kh; gq.Cl[1] = kl;
    gq.Ch[2] = vh; gq.Cl[2] = vl;
    dim3 gp(DIM / 128, NTOK / 128, 3);
    tc_gemm<128, 1><<<gp, blk, SM128>>>(xh, xl, gq, DIM, DIM, DIM, 0);

    dim3 gf(NBH, SEQ / 128);
    flash_attn<<<gf, blk, SMFA>>>(qh, ql, kh, kl, vh, vl, wah, wal);

    GParams go = {};
    go.Bh[0] = wh + 3 * DIM * DIM; go.Bl[0] = wl + 3 * DIM * DIM; go.bias[0] = bp;
    go.Cf = out;
    dim3 gop(DIM / 128, NTOK / 128, 1);
    tc_gemm<128, 0><<<gop, blk, SM128>>>(wah, wal, go, DIM, DIM, DIM, DIM);
}

// round 7
// speedup vs baseline: 1.0144x; 1.0144x over previous
#include <cuda_runtime.h>
#include <cuda_bf16.h>
#include <cstdint>
#include <math.h>

#define SEQ   1024
#define DIM   1024
#define NHEAD 16
#define HDIM  64
#define BATCH 4
#define NTOK  (BATCH*SEQ)
#define NBH   (BATCH*NHEAD)

// ---------------- scratch (allocation-free rule) ----------------
__device__ __nv_bfloat16 g_xh[NTOK*DIM],  g_xl[NTOK*DIM];
__device__ __nv_bfloat16 g_wh[4*DIM*DIM], g_wl[4*DIM*DIM];
__device__ __nv_bfloat16 g_qh[NBH*SEQ*HDIM], g_ql[NBH*SEQ*HDIM];
__device__ __nv_bfloat16 g_kh[NBH*SEQ*HDIM], g_kl[NBH*SEQ*HDIM];
__device__ __nv_bfloat16 g_vh[NBH*SEQ*HDIM], g_vl[NBH*SEQ*HDIM];
__device__ __nv_bfloat16 g_wah[NTOK*DIM], g_wal[NTOK*DIM];

// ---------------- PTX helpers ----------------
__device__ __forceinline__ uint32_t smem_u32(const void* p) {
    uint32_t a;
    asm("{ .reg .u64 t; cvta.to.shared.u64 t, %1; cvt.u32.u64 %0, t; }" : "=r"(a) : "l"(p));
    return a;
}
#define CPA16(d, s)  asm volatile("cp.async.cg.shared.global [%0], [%1], 16;" :: "r"(d), "l"(s) : "memory")
#define CPA_COMMIT() asm volatile("cp.async.commit_group;" ::: "memory")
#define CPA_WAIT(n)  asm volatile("cp.async.wait_group %0;" :: "n"(n) : "memory")

#define LDSM_X4(r, addr) \
    asm volatile("ldmatrix.sync.aligned.m8n8.x4.shared.b16 {%0,%1,%2,%3}, [%4];" \
        : "=r"((r)[0]), "=r"((r)[1]), "=r"((r)[2]), "=r"((r)[3]) : "r"(addr))
#define LDSM_X4T(r, addr) \
    asm volatile("ldmatrix.sync.aligned.m8n8.x4.trans.shared.b16 {%0,%1,%2,%3}, [%4];" \
        : "=r"((r)[0]), "=r"((r)[1]), "=r"((r)[2]), "=r"((r)[3]) : "r"(addr))

#define MMA16816(d, a, b0, b1) \
    asm volatile("mma.sync.aligned.m16n8k16.row.col.f32.bf16.bf16.f32 " \
        "{%0,%1,%2,%3}, {%4,%5,%6,%7}, {%8,%9}, {%0,%1,%2,%3};" \
        : "+f"((d)[0]), "+f"((d)[1]), "+f"((d)[2]), "+f"((d)[3]) \
        : "r"((a)[0]), "r"((a)[1]), "r"((a)[2]), "r"((a)[3]), "r"(b0), "r"(b1))

__device__ __forceinline__ uint32_t sw128(uint32_t boff) {
    return boff ^ ((boff >> 3) & 0x70);
}
__device__ __forceinline__ void split_store(__nv_bfloat16* __restrict__ hi,
                                            __nv_bfloat16* __restrict__ lo,
                                            long long off, float v0, float v1) {
    __nv_bfloat162 H, L;
    H.x = __float2bfloat16(v0); H.y = __float2bfloat16(v1);
    L.x = __float2bfloat16(v0 - __bfloat162float(H.x));
    L.y = __float2bfloat16(v1 - __bfloat162float(H.y));
    *(__nv_bfloat162*)(hi + off) = H;
    *(__nv_bfloat162*)(lo + off) = L;
}
__device__ __forceinline__ void pack_split(float a, float b, uint32_t& h, uint32_t& l) {
    __nv_bfloat162 H, L;
    H.x = __float2bfloat16(a); H.y = __float2bfloat16(b);
    L.x = __float2bfloat16(a - __bfloat162float(H.x));
    L.y = __float2bfloat16(b - __bfloat162float(H.y));
    h = *(uint32_t*)&H; l = *(uint32_t*)&L;
}

struct GParams {
    const __nv_bfloat16* Bh[3];
    const __nv_bfloat16* Bl[3];
    const float*         bias[3];
    __nv_bfloat16*       Ch[3];
    __nv_bfloat16*       Cl[3];
    float*               Cf;
};

// ---------------------------------------------------------------------------
// mma.sync bf16 GEMM, 3-term split compensation per K-chunk (hi/lo loaded once).
// C[128 x 128] per CTA, 512 thr = 16 warps (4m x 4n), warp tile 32x32.
// 3-stage cp.async pipeline.  blockIdx.z selects weight/bias/output set.
// EPI 0: fp32 out (ldc);  EPI 1: split bf16 scatter [B,H,S,Hd]
// ---------------------------------------------------------------------------
template<int EPI>
__global__ void __launch_bounds__(512, 1)
tc_gemm(const __nv_bfloat16* __restrict__ Ahi, const __nv_bfloat16* __restrict__ Alo,
        GParams gpar, int K, int lda, int ldb, int ldc)
{
    extern __shared__ char dsm[];
    constexpr int ABYTES = 128 * 128;     // 128 rows x 64 bf16
    constexpr int BBYTES = 128 * 128;
    constexpr int STG    = 2 * ABYTES + 2 * BBYTES;   // 64 KB

    const int tid    = threadIdx.x;
    const int lane   = tid & 31;
    const int wid    = tid >> 5;
    const int warp_m = wid & 3;
    const int warp_n = wid >> 2;          // 0..3
    const int row0   = blockIdx.y * 128;
    const int col0   = blockIdx.x * 128;
    const int z      = blockIdx.z;

    const __nv_bfloat16* __restrict__ Bh = gpar.Bh[z];
    const __nv_bfloat16* __restrict__ Bl = gpar.Bl[z];
    const float* __restrict__ bias       = gpar.bias[z];

    const uint32_t dyn0 = smem_u32(dsm);
    const uint32_t dyn  = (dyn0 + 1023) & ~1023u;

    const int nch = K / 64;

    auto load_chunk = [&](int c) {
        const uint32_t s = dyn + (c % 3) * STG;
        const int koff = c * 64;
        #pragma unroll
        for (int i = 0; i < 2; i++) {
            int lin = tid + i * 512;
            int r = lin >> 3, sg = lin & 7;
            uint32_t sw = sw128((uint32_t)(r * 128 + sg * 16));
            long long go = (long long)(row0 + r) * lda + koff + sg * 8;
            CPA16(s + sw,          (const void*)(Ahi + go));
            CPA16(s + ABYTES + sw, (const void*)(Alo + go));
        }
        #pragma unroll
        for (int i = 0; i < 2; i++) {
            int lin = tid + i * 512;
            int r = lin >> 3, sg = lin & 7;
            uint32_t sw = sw128((uint32_t)(r * 128 + sg * 16));
            long long go = (long long)(col0 + r) * ldb + koff + sg * 8;
            CPA16(s + 2 * ABYTES + sw,          (const void*)(Bh + go));
            CPA16(s + 2 * ABYTES + BBYTES + sw, (const void*)(Bl + go));
        }
        CPA_COMMIT();
    };

    float acc[2][4][4];
    #pragma unroll
    for (int i = 0; i < 2; i++)
        #pragma unroll
        for (int j = 0; j < 4; j++)
            #pragma unroll
            for (int q = 0; q < 4; q++) acc[i][j][q] = 0.f;

    load_chunk(0);
    load_chunk(1);

    for (int c = 0; c < nch; c++) {
        if (c + 2 < nch)      { load_chunk(c + 2); CPA_WAIT(2); }
        else if (c + 1 < nch) { CPA_WAIT(1); }
        else                  { CPA_WAIT(0); }
        __syncthreads();

        const uint32_t ah_ = dyn + (c % 3) * STG;
        const uint32_t al_ = ah_ + ABYTES;
        const uint32_t bh_ = ah_ + 2 * ABYTES;
        const uint32_t bl_ = bh_ + BBYTES;

        #pragma unroll
        for (int ks = 0; ks < 4; ks++) {
            uint32_t aH[2][4], aL[2][4];
            #pragma unroll
            for (int im = 0; im < 2; im++) {
                int r = warp_m * 32 + im * 16 + (lane & 15);
                uint32_t boff = (uint32_t)(r * 128 + ks * 32 + (lane >> 4) * 16);
                LDSM_X4(aH[im], ah_ + sw128(boff));
                LDSM_X4(aL[im], al_ + sw128(boff));
            }
            uint32_t bH0[4], bL0[4], bH1[4], bL1[4];
            {
                const int q = lane >> 3, rr = lane & 7;
                int nr0 = warp_n * 32      + ((q >> 1) << 3) + rr;
                int nr1 = warp_n * 32 + 16 + ((q >> 1) << 3) + rr;
                uint32_t bo0 = (uint32_t)(nr0 * 128 + (ks * 16 + (q & 1) * 8) * 2);
                uint32_t bo1 = (uint32_t)(nr1 * 128 + (ks * 16 + (q & 1) * 8) * 2);
                LDSM_X4(bH0, bh_ + sw128(bo0));
                LDSM_X4(bL0, bl_ + sw128(bo0));
                LDSM_X4(bH1, bh_ + sw128(bo1));
                LDSM_X4(bL1, bl_ + sw128(bo1));
            }
            // term-major across 8 independent accumulators
            #pragma unroll
            for (int im = 0; im < 2; im++) {
                MMA16816(acc[im][0], aH[im], bH0[0], bH0[1]);
                MMA16816(acc[im][1], aH[im], bH0[2], bH0[3]);
                MMA16816(acc[im][2], aH[im], bH1[0], bH1[1]);
                MMA16816(acc[im][3], aH[im], bH1[2], bH1[3]);
            }
            #pragma unroll
            for (int im = 0; im < 2; im++) {
                MMA16816(acc[im][0], aL[im], bH0[0], bH0[1]);
                MMA16816(acc[im][1], aL[im], bH0[2], bH0[3]);
                MMA16816(acc[im][2], aL[im], bH1[0], bH1[1]);
                MMA16816(acc[im][3], aL[im], bH1[2], bH1[3]);
            }
            #pragma unroll
            for (int im = 0; im < 2; im++) {
                MMA16816(acc[im][0], aH[im], bL0[0], bL0[1]);
                MMA16816(acc[im][1], aH[im], bL0[2], bL0[3]);
                MMA16816(acc[im][2], aH[im], bL1[0], bL1[1]);
                MMA16816(acc[im][3], aH[im], bL1[2], bL1[3]);
            }
        }
        __syncthreads();
    }

    const int g = lane >> 2, t = lane & 3;
    #pragma unroll
    for (int im = 0; im < 2; im++) {
        #pragma unroll
        for (int in = 0; in < 4; in++) {
            const float* ac = acc[im][in];
            const int n0 = col0 + warp_n * 32 + in * 8 + t * 2;
            #pragma unroll
            for (int half = 0; half < 2; half++) {
                const int m = row0 + warp_m * 32 + im * 16 + g + half * 8;
                float v0 = ac[half * 2]     + bias[n0];
                float v1 = ac[half * 2 + 1] + bias[n0 + 1];
                if (EPI == 0) {
                    *(float2*)(gpar.Cf + (long long)m * ldc + n0) = make_float2(v0, v1);
                } else {
                    int b = m >> 10, s = m & 1023, h = n0 >> 6, d = n0 & 63;
                    long long off = ((((long long)(b * NHEAD + h) << 10) + s) * HDIM) + d;
                    split_store(gpar.Ch[z], gpar.Cl[z], off, v0, v1);
                }
            }
        }
    }
}

// ---------------------------------------------------------------------------
// Fused flash attention, 2-stage KV pipeline, 2 CTAs/SM.
// ---------------------------------------------------------------------------
__global__ void __launch_bounds__(256, 2)
flash_attn(const __nv_bfloat16* __restrict__ qh, const __nv_bfloat16* __restrict__ ql,
           const __nv_bfloat16* __restrict__ kh, const __nv_bfloat16* __restrict__ kl,
           const __nv_bfloat16* __restrict__ vh, const __nv_bfloat16* __restrict__ vl,
           __nv_bfloat16* __restrict__ wah, __nv_bfloat16* __restrict__ wal)
{
    extern __shared__ char dsm[];
    const int tid  = threadIdx.x;
    const int lane = tid & 31;
    const int wid  = tid >> 5;
    const int z    = blockIdx.x;
    const int qrow0 = blockIdx.y * 128;

    const uint32_t dyn0 = smem_u32(dsm);
    const uint32_t dyn  = (dyn0 + 1023) & ~1023u;
    const uint32_t sQh = dyn, sQl = dyn + 16384;
    const uint32_t kvb = dyn + 32768;     // + (c&1)*32768

    const long long zoff = (long long)z * SEQ * HDIM;
    const __nv_bfloat16* Qh = qh + zoff;
    const __nv_bfloat16* Ql = ql + zoff;
    const __nv_bfloat16* Kh = kh + zoff;
    const __nv_bfloat16* Kl = kl + zoff;
    const __nv_bfloat16* Vh = vh + zoff;
    const __nv_bfloat16* Vl = vl + zoff;

    #pragma unroll
    for (int i = 0; i < 4; i++) {
        int lin = tid + i * 256;
        int r = lin >> 3, sg = lin & 7;
        uint32_t sw = sw128((uint32_t)(r * 128 + sg * 16));
        CPA16(sQh + sw, (const void*)(Qh + (long long)(qrow0 + r) * HDIM + sg * 8));
        CPA16(sQl + sw, (const void*)(Ql + (long long)(qrow0 + r) * HDIM + sg * 8));
    }
    CPA_COMMIT();

    auto load_kv = [&](int c) {
        uint32_t b = kvb + (c & 1) * 32768;
        int kv0 = c * 64;
        #pragma unroll
        for (int i = 0; i < 2; i++) {
            int lin = tid + i * 256;
            int r = lin >> 3, sg = lin & 7;
            uint32_t sw = sw128((uint32_t)(r * 128 + sg * 16));
            long long go = (long long)(kv0 + r) * HDIM + sg * 8;
            CPA16(b +         sw, (const void*)(Kh + go));
            CPA16(b + 8192  + sw, (const void*)(Kl + go));
            CPA16(b + 16384 + sw, (const void*)(Vh + go));
            CPA16(b + 24576 + sw, (const void*)(Vl + go));
        }
        CPA_COMMIT();
    };
    load_kv(0);

    const int g = lane >> 2, t = lane & 3;
    float O[8][4];
    #pragma unroll
    for (int j = 0; j < 8; j++)
        #pragma unroll
        for (int q = 0; q < 4; q++) O[j][q] = 0.f;
    float m0 = -1e30f, m1 = -1e30f, l0 = 0.f, l1 = 0.f;

    const int NKV = SEQ / 64;
    for (int c = 0; c < NKV; c++) {
        if (c + 1 < NKV) { load_kv(c + 1); CPA_WAIT(1); }
        else             { CPA_WAIT(0); }
        __syncthreads();

        const uint32_t base = kvb + (c & 1) * 32768;
        const uint32_t bKh = base, bKl = base + 8192;
        const uint32_t bVh = base + 16384, bVl = base + 24576;

        float S[8][4];
        #pragma unroll
        for (int j = 0; j < 8; j++)
            #pragma unroll
            for (int q = 0; q < 4; q++) S[j][q] = 0.f;

        #pragma unroll
        for (int ks = 0; ks < 4; ks++) {
            uint32_t aH[4], aL[4];
            {
                int r = wid * 16 + (lane & 15);
                uint32_t boff = (uint32_t)(r * 128 + ks * 32 + (lane >> 4) * 16);
                LDSM_X4(aH, sQh + sw128(boff));
                LDSM_X4(aL, sQl + sw128(boff));
            }
            #pragma unroll
            for (int gp = 0; gp < 2; gp++) {
                uint32_t bH0[4], bL0[4], bH1[4], bL1[4];
                const int q = lane >> 3, rr = lane & 7;
                int nr0 = (2 * gp)     * 16 + ((q >> 1) << 3) + rr;
                int nr1 = (2 * gp + 1) * 16 + ((q >> 1) << 3) + rr;
                uint32_t bo0 = (uint32_t)(nr0 * 128 + (ks * 16 + (q & 1) * 8) * 2);
                uint32_t bo1 = (uint32_t)(nr1 * 128 + (ks * 16 + (q & 1) * 8) * 2);
                LDSM_X4(bH0, bKh + sw128(bo0));
                LDSM_X4(bL0, bKl + sw128(bo0));
                LDSM_X4(bH1, bKh + sw128(bo1));
                LDSM_X4(bL1, bKl + sw128(bo1));
                float* S0 = S[4 * gp];     float* S1 = S[4 * gp + 1];
                float* S2 = S[4 * gp + 2]; float* S3 = S[4 * gp + 3];
                MMA16816(S0, aH, bH0[0], bH0[1]);
                MMA16816(S1, aH, bH0[2], bH0[3]);
                MMA16816(S2, aH, bH1[0], bH1[1]);
                MMA16816(S3, aH, bH1[2], bH1[3]);
                MMA16816(S0, aL, bH0[0], bH0[1]);
                MMA16816(S1, aL, bH0[2], bH0[3]);
                MMA16816(S2, aL, bH1[0], bH1[1]);
                MMA16816(S3, aL, bH1[2], bH1[3]);
                MMA16816(S0, aH, bL0[0], bL0[1]);
                MMA16816(S1, aH, bL0[2], bL0[3]);
                MMA16816(S2, aH, bL1[0], bL1[1]);
                MMA16816(S3, aH, bL1[2], bL1[3]);
            }
        }

        float mx0 = -1e30f, mx1 = -1e30f;
        #pragma unroll
        for (int j = 0; j < 8; j++) {
            S[j][0] *= 0.125f; S[j][1] *= 0.125f; S[j][2] *= 0.125f; S[j][3] *= 0.125f;
            mx0 = fmaxf(mx0, fmaxf(S[j][0], S[j][1]));
            mx1 = fmaxf(mx1, fmaxf(S[j][2], S[j][3]));
        }
        mx0 = fmaxf(mx0, __shfl_xor_sync(0xffffffffu, mx0, 1));
        mx0 = fmaxf(mx0, __shfl_xor_sync(0xffffffffu, mx0, 2));
        mx1 = fmaxf(mx1, __shfl_xor_sync(0xffffffffu, mx1, 1));
        mx1 = fmaxf(mx1, __shfl_xor_sync(0xffffffffu, mx1, 2));
        float nm0 = fmaxf(m0, mx0), nm1 = fmaxf(m1, mx1);
        float c0 = __expf(m0 - nm0), c1 = __expf(m1 - nm1);
        m0 = nm0; m1 = nm1;

        uint32_t PH[4][4], PL[4][4];
        float s0 = 0.f, s1 = 0.f;
        #pragma unroll
        for (int ck = 0; ck < 4; ck++) {
            float p00 = __expf(S[2 * ck][0] - nm0),   p01 = __expf(S[2 * ck][1] - nm0);
            float p02 = __expf(S[2 * ck][2] - nm1),   p03 = __expf(S[2 * ck][3] - nm1);
            float p10 = __expf(S[2 * ck + 1][0] - nm0), p11 = __expf(S[2 * ck + 1][1] - nm0);
            float p12 = __expf(S[2 * ck + 1][2] - nm1), p13 = __expf(S[2 * ck + 1][3] - nm1);
            s0 += p00 + p01 + p10 + p11;
            s1 += p02 + p03 + p12 + p13;
            pack_split(p00, p01, PH[ck][0], PL[ck][0]);
            pack_split(p02, p03, PH[ck][1], PL[ck][1]);
            pack_split(p10, p11, PH[ck][2], PL[ck][2]);
            pack_split(p12, p13, PH[ck][3], PL[ck][3]);
        }
        l0 = l0 * c0 + s0;
        l1 = l1 * c1 + s1;
        #pragma unroll
        for (int j = 0; j < 8; j++) {
            O[j][0] *= c0; O[j][1] *= c0; O[j][2] *= c1; O[j][3] *= c1;
        }

        #pragma unroll
        for (int ck = 0; ck < 4; ck++) {
            #pragma unroll
            for (int dp = 0; dp < 2; dp++) {
                uint32_t bH0[4], bL0[4], bH1[4], bL1[4];
                const int q = lane >> 3, rr = lane & 7;
                int kr = ck * 16 + (q & 1) * 8 + rr;
                int nc0 = (2 * dp)     * 16 + ((q >> 1) << 3);
                int nc1 = (2 * dp + 1) * 16 + ((q >> 1) << 3);
                uint32_t bo0 = (uint32_t)(kr * 128 + nc0 * 2);
                uint32_t bo1 = (uint32_t)(kr * 128 + nc1 * 2);
                LDSM_X4T(bH0, bVh + sw128(bo0));
                LDSM_X4T(bL0, bVl + sw128(bo0));
                LDSM_X4T(bH1, bVh + sw128(bo1));
                LDSM_X4T(bL1, bVl + sw128(bo1));
                float* O0 = O[4 * dp];     float* O1 = O[4 * dp + 1];
                float* O2 = O[4 * dp + 2]; float* O3 = O[4 * dp + 3];
                MMA16816(O0, PH[ck], bH0[0], bH0[1]);
                MMA16816(O1, PH[ck], bH0[2], bH0[3]);
                MMA16816(O2, PH[ck], bH1[0], bH1[1]);
                MMA16816(O3, PH[ck], bH1[2], bH1[3]);
                MMA16816(O0, PL[ck], bH0[0], bH0[1]);
                MMA16816(O1, PL[ck], bH0[2], bH0[3]);
                MMA16816(O2, PL[ck], bH1[0], bH1[1]);
                MMA16816(O3, PL[ck], bH1[2], bH1[3]);
                MMA16816(O0, PH[ck], bL0[0], bL0[1]);
                MMA16816(O1, PH[ck], bL0[2], bL0[3]);
                MMA16816(O2, PH[ck], bL1[0], bL1[1]);
                MMA16816(O3, PH[ck], bL1[2], bL1[3]);
            }
        }
        __syncthreads();
    }

    l0 += __shfl_xor_sync(0xffffffffu, l0, 1);
    l0 += __shfl_xor_sync(0xffffffffu, l0, 2);
    l1 += __shfl_xor_sync(0xffffffffu, l1, 1);
    l1 += __shfl_xor_sync(0xffffffffu, l1, 2);
    float inv0 = 1.f / l0, inv1 = 1.f / l1;

    const int b = z >> 4, h = z & 15;
    const int r0 = qrow0 + wid * 16 + g;
    #pragma unroll
    for (int j = 0; j < 8; j++) {
        int d = j * 8 + t * 2;
        long long off0 = (((long long)(b << 10) + r0) << 10) + h * HDIM + d;
        long long off1 = (((long long)(b << 10) + r0 + 8) << 10) + h * HDIM + d;
        split_store(wah, wal, off0, O[j][0] * inv0, O[j][1] * inv0);
        split_store(wah, wal, off1, O[j][2] * inv1, O[j][3] * inv1);
    }
}

// ---------------------------------------------------------------------------
struct SplitP {
    const float* in[5];
    __nv_bfloat16* hi[5];
    __nv_bfloat16* lo[5];
};

__global__ void __launch_bounds__(256)
split_all(SplitP p)
{
    int idx = blockIdx.x * 256 + threadIdx.x;
    int r, local;
    if (idx < (1 << 20)) { r = 0; local = idx; }
    else {
        int t2 = idx - (1 << 20);
        r = 1 + (t2 >> 18);
        local = t2 & ((1 << 18) - 1);
    }
    float4 v = ((const float4*)p.in[r])[local];
    __nv_bfloat16 h0 = __float2bfloat16(v.x), h1 = __float2bfloat16(v.y);
    __nv_bfloat16 h2 = __float2bfloat16(v.z), h3 = __float2bfloat16(v.w);
    __nv_bfloat162 H0; H0.x = h0; H0.y = h1;
    __nv_bfloat162 H1; H1.x = h2; H1.y = h3;
    __nv_bfloat162 L0, L1;
    L0.x = __float2bfloat16(v.x - __bfloat162float(h0));
    L0.y = __float2bfloat16(v.y - __bfloat162float(h1));
    L1.x = __float2bfloat16(v.z - __bfloat162float(h2));
    L1.y = __float2bfloat16(v.w - __bfloat162float(h3));
    ((__nv_bfloat162*)p.hi[r])[2 * local]     = H0;
    ((__nv_bfloat162*)p.hi[r])[2 * local + 1] = H1;
    ((__nv_bfloat162*)p.lo[r])[2 * local]     = L0;
    ((__nv_bfloat162*)p.lo[r])[2 * local + 1] = L1;
}

// ---------------------------------------------------------------------------
extern "C" void kernel_launch(void* const* d_in, const int* in_sizes, int n_in,
                              void* d_out, int out_size)
{
    (void)in_sizes; (void)n_in; (void)out_size;
    const float* x  = (const float*)d_in[0];
    const float* Wq = (const float*)d_in[1];
    const float* bq = (const float*)d_in[2];
    const float* Wk = (const float*)d_in[3];
    const float* bk = (const float*)d_in[4];
    const float* Wv = (const float*)d_in[5];
    const float* bv = (const float*)d_in[6];
    const float* Wp = (const float*)d_in[7];
    const float* bp = (const float*)d_in[8];
    float* out = (float*)d_out;

    __nv_bfloat16 *xh, *xl, *wh, *wl, *qh, *ql, *kh, *kl, *vh, *vl, *wah, *wal;
    cudaGetSymbolAddress((void**)&xh,  g_xh);
    cudaGetSymbolAddress((void**)&xl,  g_xl);
    cudaGetSymbolAddress((void**)&wh,  g_wh);
    cudaGetSymbolAddress((void**)&wl,  g_wl);
    cudaGetSymbolAddress((void**)&qh,  g_qh);
    cudaGetSymbolAddress((void**)&ql,  g_ql);
    cudaGetSymbolAddress((void**)&kh,  g_kh);
    cudaGetSymbolAddress((void**)&kl,  g_kl);
    cudaGetSymbolAddress((void**)&vh,  g_vh);
    cudaGetSymbolAddress((void**)&vl,  g_vl);
    cudaGetSymbolAddress((void**)&wah, g_wah);
    cudaGetSymbolAddress((void**)&wal, g_wal);

    const int SM128 = 3 * 65536 + 1024;            // 197632
    const int SMFA  = 32768 + 2 * 32768 + 1024;    // 99328  (2 CTAs/SM)
    cudaFuncSetAttribute(tc_gemm<1>, cudaFuncAttributeMaxDynamicSharedMemorySize, SM128);
    cudaFuncSetAttribute(tc_gemm<0>, cudaFuncAttributeMaxDynamicSharedMemorySize, SM128);
    cudaFuncSetAttribute(flash_attn, cudaFuncAttributeMaxDynamicSharedMemorySize, SMFA);

    SplitP sp;
    sp.in[0] = x;  sp.hi[0] = xh;                  sp.lo[0] = xl;
    sp.in[1] = Wq; sp.hi[1] = wh + 0 * DIM * DIM;  sp.lo[1] = wl + 0 * DIM * DIM;
    sp.in[2] = Wk; sp.hi[2] = wh + 1 * DIM * DIM;  sp.lo[2] = wl + 1 * DIM * DIM;
    sp.in[3] = Wv; sp.hi[3] = wh + 2 * DIM * DIM;  sp.lo[3] = wl + 2 * DIM * DIM;
    sp.in[4] = Wp; sp.hi[4] = wh + 3 * DIM * DIM;  sp.lo[4] = wl + 3 * DIM * DIM;
    split_all<<<(1 << 20) / 256 + 4 * ((1 << 18) / 256), 256>>>(sp);

    GParams gq = {};
    gq.Bh[0] = wh + 0 * DIM * DIM; gq.Bl[0] = wl + 0 * DIM * DIM; gq.bias[0] = bq;
    gq.Bh[1] = wh + 1 * DIM * DIM; gq.Bl[1] = wl + 1 * DIM * DIM; gq.bias[1] = bk;
    gq.Bh[2] = wh + 2 * DIM * DIM; gq.Bl[2] = wl + 2 * DIM * DIM; gq.bias[2] = bv;
    gq.Ch[0] = qh; gq.Cl[0] = ql;
    gq.Ch[1] = kh; gq.Cl[1] = kl;
    gq.Ch[2] = vh; gq.Cl[2] = vl;
    dim3 gp(DIM / 128, NTOK / 128, 3);
    tc_gemm<1><<<gp, 512, SM128>>>(xh, xl, gq, DIM, DIM, DIM, 0);

    dim3 gf(NBH, SEQ / 128);
    flash_attn<<<gf, 256, SMFA>>>(qh, ql, kh, kl, vh, vl, wah, wal);

    GParams go = {};
    go.Bh[0] = wh + 3 * DIM * DIM; go.Bl[0] = wl + 3 * DIM * DIM; go.bias[0] = bp;
    go.Cf = out;
    dim3 gop(DIM / 128, NTOK / 128, 1);
    tc_gemm<0><<<gop, 512, SM128>>>(wah, wal, go, DIM, DIM, DIM, DIM);
}

// round 8
// speedup vs baseline: 1.0963x; 1.0808x over previous
#include <cuda_runtime.h>
#include <cuda_bf16.h>
#include <cstdint>
#include <math.h>

#define SEQ   1024
#define DIM   1024
#define NHEAD 16
#define HDIM  64
#define BATCH 4
#define NTOK  (BATCH*SEQ)
#define NBH   (BATCH*NHEAD)

// ---------------- scratch (allocation-free rule) ----------------
__device__ __nv_bfloat16 g_xh[NTOK*DIM],  g_xl[NTOK*DIM];
__device__ __nv_bfloat16 g_wh[4*DIM*DIM], g_wl[4*DIM*DIM];
__device__ __nv_bfloat16 g_qh[NBH*SEQ*HDIM], g_ql[NBH*SEQ*HDIM];
__device__ __nv_bfloat16 g_kh[NBH*SEQ*HDIM], g_kl[NBH*SEQ*HDIM];
__device__ __nv_bfloat16 g_vh[NBH*SEQ*HDIM], g_vl[NBH*SEQ*HDIM];
__device__ __nv_bfloat16 g_wah[NTOK*DIM], g_wal[NTOK*DIM];

// ---------------- PTX helpers ----------------
__device__ __forceinline__ uint32_t smem_u32(const void* p) {
    uint32_t a;
    asm("{ .reg .u64 t; cvta.to.shared.u64 t, %1; cvt.u32.u64 %0, t; }" : "=r"(a) : "l"(p));
    return a;
}
#define CPA16(d, s)  asm volatile("cp.async.cg.shared.global [%0], [%1], 16;" :: "r"(d), "l"(s) : "memory")
#define CPA_COMMIT() asm volatile("cp.async.commit_group;" ::: "memory")
#define CPA_WAIT(n)  asm volatile("cp.async.wait_group %0;" :: "n"(n) : "memory")

#define LDSM_X4(r, addr) \
    asm volatile("ldmatrix.sync.aligned.m8n8.x4.shared.b16 {%0,%1,%2,%3}, [%4];" \
        : "=r"((r)[0]), "=r"((r)[1]), "=r"((r)[2]), "=r"((r)[3]) : "r"(addr))
#define LDSM_X4T(r, addr) \
    asm volatile("ldmatrix.sync.aligned.m8n8.x4.trans.shared.b16 {%0,%1,%2,%3}, [%4];" \
        : "=r"((r)[0]), "=r"((r)[1]), "=r"((r)[2]), "=r"((r)[3]) : "r"(addr))

#define MMA16816(d, a, b0, b1) \
    asm volatile("mma.sync.aligned.m16n8k16.row.col.f32.bf16.bf16.f32 " \
        "{%0,%1,%2,%3}, {%4,%5,%6,%7}, {%8,%9}, {%0,%1,%2,%3};" \
        : "+f"((d)[0]), "+f"((d)[1]), "+f"((d)[2]), "+f"((d)[3]) \
        : "r"((a)[0]), "r"((a)[1]), "r"((a)[2]), "r"((a)[3]), "r"(b0), "r"(b1))

__device__ __forceinline__ uint32_t sw128(uint32_t boff) {
    return boff ^ ((boff >> 3) & 0x70);
}
__device__ __forceinline__ void split_store(__nv_bfloat16* __restrict__ hi,
                                            __nv_bfloat16* __restrict__ lo,
                                            long long off, float v0, float v1) {
    __nv_bfloat162 H, L;
    H.x = __float2bfloat16(v0); H.y = __float2bfloat16(v1);
    L.x = __float2bfloat16(v0 - __bfloat162float(H.x));
    L.y = __float2bfloat16(v1 - __bfloat162float(H.y));
    *(__nv_bfloat162*)(hi + off) = H;
    *(__nv_bfloat162*)(lo + off) = L;
}
__device__ __forceinline__ void pack_split(float a, float b, uint32_t& h, uint32_t& l) {
    __nv_bfloat162 H, L;
    H.x = __float2bfloat16(a); H.y = __float2bfloat16(b);
    L.x = __float2bfloat16(a - __bfloat162float(H.x));
    L.y = __float2bfloat16(b - __bfloat162float(H.y));
    h = *(uint32_t*)&H; l = *(uint32_t*)&L;
}

struct GParams {
    const __nv_bfloat16* Bh[3];
    const __nv_bfloat16* Bl[3];
    const float*         bias[3];
    __nv_bfloat16*       Ch[3];
    __nv_bfloat16*       Cl[3];
    float*               Cf;
};

// ---------------------------------------------------------------------------
// mma.sync bf16 GEMM, 3-term split compensation per K-chunk (hi/lo loaded once).
// C[128 x 64] per CTA, 256 thr = 8 warps (4m x 2n), warp tile 32x32.
// 2-stage cp.async pipeline, 2 CTAs/SM (independent barrier domains).
// EPI 0: fp32 out (ldc);  EPI 1: split bf16 scatter [B,H,S,Hd]
// ---------------------------------------------------------------------------
template<int EPI>
__global__ void __launch_bounds__(256, 2)
tc_gemm(const __nv_bfloat16* __restrict__ Ahi, const __nv_bfloat16* __restrict__ Alo,
        GParams gpar, int K, int lda, int ldb, int ldc)
{
    extern __shared__ char dsm[];
    constexpr int ABYTES = 128 * 128;              // 128 rows x 64 bf16
    constexpr int BBYTES = 64 * 128;               // 64 rows x 64 bf16
    constexpr int STG    = 2 * ABYTES + 2 * BBYTES;  // 48 KB

    const int tid    = threadIdx.x;
    const int lane   = tid & 31;
    const int wid    = tid >> 5;
    const int warp_m = wid & 3;
    const int warp_n = wid >> 2;                   // 0..1
    const int row0   = blockIdx.y * 128;
    const int col0   = blockIdx.x * 64;
    const int z      = blockIdx.z;

    const __nv_bfloat16* __restrict__ Bh = gpar.Bh[z];
    const __nv_bfloat16* __restrict__ Bl = gpar.Bl[z];
    const float* __restrict__ bias       = gpar.bias[z];

    const uint32_t dyn0 = smem_u32(dsm);
    const uint32_t dyn  = (dyn0 + 1023) & ~1023u;

    const int nch = K / 64;

    auto load_chunk = [&](int c) {
        const uint32_t s = dyn + (c & 1) * STG;
        const int koff = c * 64;
        #pragma unroll
        for (int i = 0; i < 4; i++) {
            int lin = tid + i * 256;
            int r = lin >> 3, sg = lin & 7;
            uint32_t sw = sw128((uint32_t)(r * 128 + sg * 16));
            long long go = (long long)(row0 + r) * lda + koff + sg * 8;
            CPA16(s + sw,          (const void*)(Ahi + go));
            CPA16(s + ABYTES + sw, (const void*)(Alo + go));
        }
        #pragma unroll
        for (int i = 0; i < 2; i++) {
            int lin = tid + i * 256;
            int r = lin >> 3, sg = lin & 7;
            uint32_t sw = sw128((uint32_t)(r * 128 + sg * 16));
            long long go = (long long)(col0 + r) * ldb + koff + sg * 8;
            CPA16(s + 2 * ABYTES + sw,          (const void*)(Bh + go));
            CPA16(s + 2 * ABYTES + BBYTES + sw, (const void*)(Bl + go));
        }
        CPA_COMMIT();
    };

    float acc[2][4][4];
    #pragma unroll
    for (int i = 0; i < 2; i++)
        #pragma unroll
        for (int j = 0; j < 4; j++)
            #pragma unroll
            for (int q = 0; q < 4; q++) acc[i][j][q] = 0.f;

    load_chunk(0);

    for (int c = 0; c < nch; c++) {
        if (c + 1 < nch) { load_chunk(c + 1); CPA_WAIT(1); }
        else             { CPA_WAIT(0); }
        __syncthreads();

        const uint32_t ah_ = dyn + (c & 1) * STG;
        const uint32_t al_ = ah_ + ABYTES;
        const uint32_t bh_ = ah_ + 2 * ABYTES;
        const uint32_t bl_ = bh_ + BBYTES;

        #pragma unroll
        for (int ks = 0; ks < 4; ks++) {
            uint32_t aH[2][4], aL[2][4];
            #pragma unroll
            for (int im = 0; im < 2; im++) {
                int r = warp_m * 32 + im * 16 + (lane & 15);
                uint32_t boff = (uint32_t)(r * 128 + ks * 32 + (lane >> 4) * 16);
                LDSM_X4(aH[im], ah_ + sw128(boff));
                LDSM_X4(aL[im], al_ + sw128(boff));
            }
            uint32_t bH0[4], bL0[4], bH1[4], bL1[4];
            {
                const int q = lane >> 3, rr = lane & 7;
                int nr0 = warp_n * 32      + ((q >> 1) << 3) + rr;
                int nr1 = warp_n * 32 + 16 + ((q >> 1) << 3) + rr;
                uint32_t bo0 = (uint32_t)(nr0 * 128 + (ks * 16 + (q & 1) * 8) * 2);
                uint32_t bo1 = (uint32_t)(nr1 * 128 + (ks * 16 + (q & 1) * 8) * 2);
                LDSM_X4(bH0, bh_ + sw128(bo0));
                LDSM_X4(bL0, bl_ + sw128(bo0));
                LDSM_X4(bH1, bh_ + sw128(bo1));
                LDSM_X4(bL1, bl_ + sw128(bo1));
            }
            // term-major across 8 independent accumulators
            #pragma unroll
            for (int im = 0; im < 2; im++) {
                MMA16816(acc[im][0], aH[im], bH0[0], bH0[1]);
                MMA16816(acc[im][1], aH[im], bH0[2], bH0[3]);
                MMA16816(acc[im][2], aH[im], bH1[0], bH1[1]);
                MMA16816(acc[im][3], aH[im], bH1[2], bH1[3]);
            }
            #pragma unroll
            for (int im = 0; im < 2; im++) {
                MMA16816(acc[im][0], aL[im], bH0[0], bH0[1]);
                MMA16816(acc[im][1], aL[im], bH0[2], bH0[3]);
                MMA16816(acc[im][2], aL[im], bH1[0], bH1[1]);
                MMA16816(acc[im][3], aL[im], bH1[2], bH1[3]);
            }
            #pragma unroll
            for (int im = 0; im < 2; im++) {
                MMA16816(acc[im][0], aH[im], bL0[0], bL0[1]);
                MMA16816(acc[im][1], aH[im], bL0[2], bL0[3]);
                MMA16816(acc[im][2], aH[im], bL1[0], bL1[1]);
                MMA16816(acc[im][3], aH[im], bL1[2], bL1[3]);
            }
        }
        __syncthreads();
    }

    const int g = lane >> 2, t = lane & 3;
    #pragma unroll
    for (int im = 0; im < 2; im++) {
        #pragma unroll
        for (int in = 0; in < 4; in++) {
            const float* ac = acc[im][in];
            const int n0 = col0 + warp_n * 32 + in * 8 + t * 2;
            #pragma unroll
            for (int half = 0; half < 2; half++) {
                const int m = row0 + warp_m * 32 + im * 16 + g + half * 8;
                float v0 = ac[half * 2]     + bias[n0];
                float v1 = ac[half * 2 + 1] + bias[n0 + 1];
                if (EPI == 0) {
                    *(float2*)(gpar.Cf + (long long)m * ldc + n0) = make_float2(v0, v1);
                } else {
                    int b = m >> 10, s = m & 1023, h = n0 >> 6, d = n0 & 63;
                    long long off = ((((long long)(b * NHEAD + h) << 10) + s) * HDIM) + d;
                    split_store(gpar.Ch[z], gpar.Cl[z], off, v0, v1);
                }
            }
        }
    }
}

// ---------------------------------------------------------------------------
// Fused flash attention, 2-stage KV pipeline, 2 CTAs/SM.
// ---------------------------------------------------------------------------
__global__ void __launch_bounds__(256, 2)
flash_attn(const __nv_bfloat16* __restrict__ qh, const __nv_bfloat16* __restrict__ ql,
           const __nv_bfloat16* __restrict__ kh, const __nv_bfloat16* __restrict__ kl,
           const __nv_bfloat16* __restrict__ vh, const __nv_bfloat16* __restrict__ vl,
           __nv_bfloat16* __restrict__ wah, __nv_bfloat16* __restrict__ wal)
{
    extern __shared__ char dsm[];
    const int tid  = threadIdx.x;
    const int lane = tid & 31;
    const int wid  = tid >> 5;
    const int z    = blockIdx.x;
    const int qrow0 = blockIdx.y * 128;

    const uint32_t dyn0 = smem_u32(dsm);
    const uint32_t dyn  = (dyn0 + 1023) & ~1023u;
    const uint32_t sQh = dyn, sQl = dyn + 16384;
    const uint32_t kvb = dyn + 32768;

    const long long zoff = (long long)z * SEQ * HDIM;
    const __nv_bfloat16* Qh = qh + zoff;
    const __nv_bfloat16* Ql = ql + zoff;
    const __nv_bfloat16* Kh = kh + zoff;
    const __nv_bfloat16* Kl = kl + zoff;
    const __nv_bfloat16* Vh = vh + zoff;
    const __nv_bfloat16* Vl = vl + zoff;

    #pragma unroll
    for (int i = 0; i < 4; i++) {
        int lin = tid + i * 256;
        int r = lin >> 3, sg = lin & 7;
        uint32_t sw = sw128((uint32_t)(r * 128 + sg * 16));
        CPA16(sQh + sw, (const void*)(Qh + (long long)(qrow0 + r) * HDIM + sg * 8));
        CPA16(sQl + sw, (const void*)(Ql + (long long)(qrow0 + r) * HDIM + sg * 8));
    }
    CPA_COMMIT();

    auto load_kv = [&](int c) {
        uint32_t b = kvb + (c & 1) * 32768;
        int kv0 = c * 64;
        #pragma unroll
        for (int i = 0; i < 2; i++) {
            int lin = tid + i * 256;
            int r = lin >> 3, sg = lin & 7;
            uint32_t sw = sw128((uint32_t)(r * 128 + sg * 16));
            long long go = (long long)(kv0 + r) * HDIM + sg * 8;
            CPA16(b +         sw, (const void*)(Kh + go));
            CPA16(b + 8192  + sw, (const void*)(Kl + go));
            CPA16(b + 16384 + sw, (const void*)(Vh + go));
            CPA16(b + 24576 + sw, (const void*)(Vl + go));
        }
        CPA_COMMIT();
    };
    load_kv(0);

    const int g = lane >> 2, t = lane & 3;
    float O[8][4];
    #pragma unroll
    for (int j = 0; j < 8; j++)
        #pragma unroll
        for (int q = 0; q < 4; q++) O[j][q] = 0.f;
    float m0 = -1e30f, m1 = -1e30f, l0 = 0.f, l1 = 0.f;

    const int NKV = SEQ / 64;
    for (int c = 0; c < NKV; c++) {
        if (c + 1 < NKV) { load_kv(c + 1); CPA_WAIT(1); }
        else             { CPA_WAIT(0); }
        __syncthreads();

        const uint32_t base = kvb + (c & 1) * 32768;
        const uint32_t bKh = base, bKl = base + 8192;
        const uint32_t bVh = base + 16384, bVl = base + 24576;

        float S[8][4];
        #pragma unroll
        for (int j = 0; j < 8; j++)
            #pragma unroll
            for (int q = 0; q < 4; q++) S[j][q] = 0.f;

        #pragma unroll
        for (int ks = 0; ks < 4; ks++) {
            uint32_t aH[4], aL[4];
            {
                int r = wid * 16 + (lane & 15);
                uint32_t boff = (uint32_t)(r * 128 + ks * 32 + (lane >> 4) * 16);
                LDSM_X4(aH, sQh + sw128(boff));
                LDSM_X4(aL, sQl + sw128(boff));
            }
            #pragma unroll
            for (int gp = 0; gp < 2; gp++) {
                uint32_t bH0[4], bL0[4], bH1[4], bL1[4];
                const int q = lane >> 3, rr = lane & 7;
                int nr0 = (2 * gp)     * 16 + ((q >> 1) << 3) + rr;
                int nr1 = (2 * gp + 1) * 16 + ((q >> 1) << 3) + rr;
                uint32_t bo0 = (uint32_t)(nr0 * 128 + (ks * 16 + (q & 1) * 8) * 2);
                uint32_t bo1 = (uint32_t)(nr1 * 128 + (ks * 16 + (q & 1) * 8) * 2);
                LDSM_X4(bH0, bKh + sw128(bo0));
                LDSM_X4(bL0, bKl + sw128(bo0));
                LDSM_X4(bH1, bKh + sw128(bo1));
                LDSM_X4(bL1, bKl + sw128(bo1));
                float* S0 = S[4 * gp];     float* S1 = S[4 * gp + 1];
                float* S2 = S[4 * gp + 2]; float* S3 = S[4 * gp + 3];
                MMA16816(S0, aH, bH0[0], bH0[1]);
                MMA16816(S1, aH, bH0[2], bH0[3]);
                MMA16816(S2, aH, bH1[0], bH1[1]);
                MMA16816(S3, aH, bH1[2], bH1[3]);
                MMA16816(S0, aL, bH0[0], bH0[1]);
                MMA16816(S1, aL, bH0[2], bH0[3]);
                MMA16816(S2, aL, bH1[0], bH1[1]);
                MMA16816(S3, aL, bH1[2], bH1[3]);
                MMA16816(S0, aH, bL0[0], bL0[1]);
                MMA16816(S1, aH, bL0[2], bL0[3]);
                MMA16816(S2, aH, bL1[0], bL1[1]);
                MMA16816(S3, aH, bL1[2], bL1[3]);
            }
        }

        float mx0 = -1e30f, mx1 = -1e30f;
        #pragma unroll
        for (int j = 0; j < 8; j++) {
            S[j][0] *= 0.125f; S[j][1] *= 0.125f; S[j][2] *= 0.125f; S[j][3] *= 0.125f;
            mx0 = fmaxf(mx0, fmaxf(S[j][0], S[j][1]));
            mx1 = fmaxf(mx1, fmaxf(S[j][2], S[j][3]));
        }
        mx0 = fmaxf(mx0, __shfl_xor_sync(0xffffffffu, mx0, 1));
        mx0 = fmaxf(mx0, __shfl_xor_sync(0xffffffffu, mx0, 2));
        mx1 = fmaxf(mx1, __shfl_xor_sync(0xffffffffu, mx1, 1));
        mx1 = fmaxf(mx1, __shfl_xor_sync(0xffffffffu, mx1, 2));
        float nm0 = fmaxf(m0, mx0), nm1 = fmaxf(m1, mx1);
        float c0 = __expf(m0 - nm0), c1 = __expf(m1 - nm1);
        m0 = nm0; m1 = nm1;

        uint32_t PH[4][4], PL[4][4];
        float s0 = 0.f, s1 = 0.f;
        #pragma unroll
        for (int ck = 0; ck < 4; ck++) {
            float p00 = __expf(S[2 * ck][0] - nm0),   p01 = __expf(S[2 * ck][1] - nm0);
            float p02 = __expf(S[2 * ck][2] - nm1),   p03 = __expf(S[2 * ck][3] - nm1);
            float p10 = __expf(S[2 * ck + 1][0] - nm0), p11 = __expf(S[2 * ck + 1][1] - nm0);
            float p12 = __expf(S[2 * ck + 1][2] - nm1), p13 = __expf(S[2 * ck + 1][3] - nm1);
            s0 += p00 + p01 + p10 + p11;
            s1 += p02 + p03 + p12 + p13;
            pack_split(p00, p01, PH[ck][0], PL[ck][0]);
            pack_split(p02, p03, PH[ck][1], PL[ck][1]);
            pack_split(p10, p11, PH[ck][2], PL[ck][2]);
            pack_split(p12, p13, PH[ck][3], PL[ck][3]);
        }
        l0 = l0 * c0 + s0;
        l1 = l1 * c1 + s1;
        #pragma unroll
        for (int j = 0; j < 8; j++) {
            O[j][0] *= c0; O[j][1] *= c0; O[j][2] *= c1; O[j][3] *= c1;
        }

        #pragma unroll
        for (int ck = 0; ck < 4; ck++) {
            #pragma unroll
            for (int dp = 0; dp < 2; dp++) {
                uint32_t bH0[4], bL0[4], bH1[4], bL1[4];
                const int q = lane >> 3, rr = lane & 7;
                int kr = ck * 16 + (q & 1) * 8 + rr;
                int nc0 = (2 * dp)     * 16 + ((q >> 1) << 3);
                int nc1 = (2 * dp + 1) * 16 + ((q >> 1) << 3);
                uint32_t bo0 = (uint32_t)(kr * 128 + nc0 * 2);
                uint32_t bo1 = (uint32_t)(kr * 128 + nc1 * 2);
                LDSM_X4T(bH0, bVh + sw128(bo0));
                LDSM_X4T(bL0, bVl + sw128(bo0));
                LDSM_X4T(bH1, bVh + sw128(bo1));
                LDSM_X4T(bL1, bVl + sw128(bo1));
                float* O0 = O[4 * dp];     float* O1 = O[4 * dp + 1];
                float* O2 = O[4 * dp + 2]; float* O3 = O[4 * dp + 3];
                MMA16816(O0, PH[ck], bH0[0], bH0[1]);
                MMA16816(O1, PH[ck], bH0[2], bH0[3]);
                MMA16816(O2, PH[ck], bH1[0], bH1[1]);
                MMA16816(O3, PH[ck], bH1[2], bH1[3]);
                MMA16816(O0, PL[ck], bH0[0], bH0[1]);
                MMA16816(O1, PL[ck], bH0[2], bH0[3]);
                MMA16816(O2, PL[ck], bH1[0], bH1[1]);
                MMA16816(O3, PL[ck], bH1[2], bH1[3]);
                MMA16816(O0, PH[ck], bL0[0], bL0[1]);
                MMA16816(O1, PH[ck], bL0[2], bL0[3]);
                MMA16816(O2, PH[ck], bL1[0], bL1[1]);
                MMA16816(O3, PH[ck], bL1[2], bL1[3]);
            }
        }
        __syncthreads();
    }

    l0 += __shfl_xor_sync(0xffffffffu, l0, 1);
    l0 += __shfl_xor_sync(0xffffffffu, l0, 2);
    l1 += __shfl_xor_sync(0xffffffffu, l1, 1);
    l1 += __shfl_xor_sync(0xffffffffu, l1, 2);
    float inv0 = 1.f / l0, inv1 = 1.f / l1;

    const int b = z >> 4, h = z & 15;
    const int r0 = qrow0 + wid * 16 + g;
    #pragma unroll
    for (int j = 0; j < 8; j++) {
        int d = j * 8 + t * 2;
        long long off0 = (((long long)(b << 10) + r0) << 10) + h * HDIM + d;
        long long off1 = (((long long)(b << 10) + r0 + 8) << 10) + h * HDIM + d;
        split_store(wah, wal, off0, O[j][0] * inv0, O[j][1] * inv0);
        split_store(wah, wal, off1, O[j][2] * inv1, O[j][3] * inv1);
    }
}

// ---------------------------------------------------------------------------
struct SplitP {
    const float* in[5];
    __nv_bfloat16* hi[5];
    __nv_bfloat16* lo[5];
};

__global__ void __launch_bounds__(256)
split_all(SplitP p)
{
    int idx = blockIdx.x * 256 + threadIdx.x;
    int r, local;
    if (idx < (1 << 20)) { r = 0; local = idx; }
    else {
        int t2 = idx - (1 << 20);
        r = 1 + (t2 >> 18);
        local = t2 & ((1 << 18) - 1);
    }
    float4 v = ((const float4*)p.in[r])[local];
    __nv_bfloat16 h0 = __float2bfloat16(v.x), h1 = __float2bfloat16(v.y);
    __nv_bfloat16 h2 = __float2bfloat16(v.z), h3 = __float2bfloat16(v.w);
    __nv_bfloat162 H0; H0.x = h0; H0.y = h1;
    __nv_bfloat162 H1; H1.x = h2; H1.y = h3;
    __nv_bfloat162 L0, L1;
    L0.x = __float2bfloat16(v.x - __bfloat162float(h0));
    L0.y = __float2bfloat16(v.y - __bfloat162float(h1));
    L1.x = __float2bfloat16(v.z - __bfloat162float(h2));
    L1.y = __float2bfloat16(v.w - __bfloat162float(h3));
    ((__nv_bfloat162*)p.hi[r])[2 * local]     = H0;
    ((__nv_bfloat162*)p.hi[r])[2 * local + 1] = H1;
    ((__nv_bfloat162*)p.lo[r])[2 * local]     = L0;
    ((__nv_bfloat162*)p.lo[r])[2 * local + 1] = L1;
}

// ---------------------------------------------------------------------------
extern "C" void kernel_launch(void* const* d_in, const int* in_sizes, int n_in,
                              void* d_out, int out_size)
{
    (void)in_sizes; (void)n_in; (void)out_size;
    const float* x  = (const float*)d_in[0];
    const float* Wq = (const float*)d_in[1];
    const float* bq = (const float*)d_in[2];
    const float* Wk = (const float*)d_in[3];
    const float* bk = (const float*)d_in[4];
    const float* Wv = (const float*)d_in[5];
    const float* bv = (const float*)d_in[6];
    const float* Wp = (const float*)d_in[7];
    const float* bp = (const float*)d_in[8];
    float* out = (float*)d_out;

    __nv_bfloat16 *xh, *xl, *wh, *wl, *qh, *ql, *kh, *kl, *vh, *vl, *wah, *wal;
    cudaGetSymbolAddress((void**)&xh,  g_xh);
    cudaGetSymbolAddress((void**)&xl,  g_xl);
    cudaGetSymbolAddress((void**)&wh,  g_wh);
    cudaGetSymbolAddress((void**)&wl,  g_wl);
    cudaGetSymbolAddress((void**)&qh,  g_qh);
    cudaGetSymbolAddress((void**)&ql,  g_ql);
    cudaGetSymbolAddress((void**)&kh,  g_kh);
    cudaGetSymbolAddress((void**)&kl,  g_kl);
    cudaGetSymbolAddress((void**)&vh,  g_vh);
    cudaGetSymbolAddress((void**)&vl,  g_vl);
    cudaGetSymbolAddress((void**)&wah, g_wah);
    cudaGetSymbolAddress((void**)&wal, g_wal);

    const int SMGM = 2 * (2 * 16384 + 2 * 8192) + 1024;  // 99328 (2 CTAs/SM)
    const int SMFA = 32768 + 2 * 32768 + 1024;           // 99328 (2 CTAs/SM)
    cudaFuncSetAttribute(tc_gemm<1>, cudaFuncAttributeMaxDynamicSharedMemorySize, SMGM);
    cudaFuncSetAttribute(tc_gemm<0>, cudaFuncAttributeMaxDynamicSharedMemorySize, SMGM);
    cudaFuncSetAttribute(flash_attn, cudaFuncAttributeMaxDynamicSharedMemorySize, SMFA);

    SplitP sp;
    sp.in[0] = x;  sp.hi[0] = xh;                  sp.lo[0] = xl;
    sp.in[1] = Wq; sp.hi[1] = wh + 0 * DIM * DIM;  sp.lo[1] = wl + 0 * DIM * DIM;
    sp.in[2] = Wk; sp.hi[2] = wh + 1 * DIM * DIM;  sp.lo[2] = wl + 1 * DIM * DIM;
    sp.in[3] = Wv; sp.hi[3] = wh + 2 * DIM * DIM;  sp.lo[3] = wl + 2 * DIM * DIM;
    sp.in[4] = Wp; sp.hi[4] = wh + 3 * DIM * DIM;  sp.lo[4] = wl + 3 * DIM * DIM;
    split_all<<<(1 << 20) / 256 + 4 * ((1 << 18) / 256), 256>>>(sp);

    GParams gq = {};
    gq.Bh[0] = wh + 0 * DIM * DIM; gq.Bl[0] = wl + 0 * DIM * DIM; gq.bias[0] = bq;
    gq.Bh[1] = wh + 1 * DIM * DIM; gq.Bl[1] = wl + 1 * DIM * DIM; gq.bias[1] = bk;
    gq.Bh[2] = wh + 2 * DIM * DIM; gq.Bl[2] = wl + 2 * DIM * DIM; gq.bias[2] = bv;
    gq.Ch[0] = qh; gq.Cl[0] = ql;
    gq.Ch[1] = kh; gq.Cl[1] = kl;
    gq.Ch[2] = vh; gq.Cl[2] = vl;
    dim3 gp(DIM / 64, NTOK / 128, 3);
    tc_gemm<1><<<gp, 256, SMGM>>>(xh, xl, gq, DIM, DIM, DIM, 0);

    dim3 gf(NBH, SEQ / 128);
    flash_attn<<<gf, 256, SMFA>>>(qh, ql, kh, kl, vh, vl, wah, wal);

    GParams go = {};
    go.Bh[0] = wh + 3 * DIM * DIM; go.Bl[0] = wl + 3 * DIM * DIM; go.bias[0] = bp;
    go.Cf = out;
    dim3 gop(DIM / 64, NTOK / 128, 1);
    tc_gemm<0><<<gop, 256, SMGM>>>(wah, wal, go, DIM, DIM, DIM, DIM);
}

// round 9
// speedup vs baseline: 1.5209x; 1.3873x over previous
#include <cuda_runtime.h>
#include <cuda_fp16.h>
#include <cstdint>
#include <math.h>

#define SEQ   1024
#define DIM   1024
#define NHEAD 16
#define HDIM  64
#define BATCH 4
#define NTOK  (BATCH*SEQ)
#define NBH   (BATCH*NHEAD)

// ---------------- scratch (allocation-free rule) ----------------
__device__ __half g_xh[NTOK*DIM],  g_xl[NTOK*DIM];      // x split (A operand)
__device__ __half g_wh[4*DIM*DIM];                      // weights, fp16 single (B)
__device__ __half g_qh[NBH*SEQ*HDIM], g_ql[NBH*SEQ*HDIM]; // Q split (A)
__device__ __half g_kh[NBH*SEQ*HDIM];                   // K fp16 single (B)
__device__ __half g_vh[NBH*SEQ*HDIM];                   // V fp16 single (B)
__device__ __half g_wah[NTOK*DIM], g_wal[NTOK*DIM];     // wa split (A)

// ---------------- PTX helpers ----------------
__device__ __forceinline__ uint32_t smem_u32(const void* p) {
    uint32_t a;
    asm("{ .reg .u64 t; cvta.to.shared.u64 t, %1; cvt.u32.u64 %0, t; }" : "=r"(a) : "l"(p));
    return a;
}
#define CPA16(d, s)  asm volatile("cp.async.cg.shared.global [%0], [%1], 16;" :: "r"(d), "l"(s) : "memory")
#define CPA_COMMIT() asm volatile("cp.async.commit_group;" ::: "memory")
#define CPA_WAIT(n)  asm volatile("cp.async.wait_group %0;" :: "n"(n) : "memory")

#define LDSM_X4(r, addr) \
    asm volatile("ldmatrix.sync.aligned.m8n8.x4.shared.b16 {%0,%1,%2,%3}, [%4];" \
        : "=r"((r)[0]), "=r"((r)[1]), "=r"((r)[2]), "=r"((r)[3]) : "r"(addr))
#define LDSM_X4T(r, addr) \
    asm volatile("ldmatrix.sync.aligned.m8n8.x4.trans.shared.b16 {%0,%1,%2,%3}, [%4];" \
        : "=r"((r)[0]), "=r"((r)[1]), "=r"((r)[2]), "=r"((r)[3]) : "r"(addr))

#define MMA16816(d, a, b0, b1) \
    asm volatile("mma.sync.aligned.m16n8k16.row.col.f32.f16.f16.f32 " \
        "{%0,%1,%2,%3}, {%4,%5,%6,%7}, {%8,%9}, {%0,%1,%2,%3};" \
        : "+f"((d)[0]), "+f"((d)[1]), "+f"((d)[2]), "+f"((d)[3]) \
        : "r"((a)[0]), "r"((a)[1]), "r"((a)[2]), "r"((a)[3]), "r"(b0), "r"(b1))

__device__ __forceinline__ uint32_t sw128(uint32_t boff) {
    return boff ^ ((boff >> 3) & 0x70);
}
__device__ __forceinline__ void split_store_h(__half* __restrict__ hi,
                                              __half* __restrict__ lo,
                                              long long off, float v0, float v1) {
    __half h0 = __float2half_rn(v0), h1 = __float2half_rn(v1);
    __half2 H; H.x = h0; H.y = h1;
    __half2 L;
    L.x = __float2half_rn(v0 - __half2float(h0));
    L.y = __float2half_rn(v1 - __half2float(h1));
    *(__half2*)(hi + off) = H;
    *(__half2*)(lo + off) = L;
}
__device__ __forceinline__ void pack_split_h(float a, float b, uint32_t& h, uint32_t& l) {
    __half h0 = __float2half_rn(a), h1 = __float2half_rn(b);
    __half2 H; H.x = h0; H.y = h1;
    __half2 L;
    L.x = __float2half_rn(a - __half2float(h0));
    L.y = __float2half_rn(b - __half2float(h1));
    h = *(uint32_t*)&H; l = *(uint32_t*)&L;
}

struct GParams {
    const __half* Bh[3];
    const float*  bias[3];
    __half*       Ch[3];
    __half*       Cl[3];     // nullptr -> single fp16 store
    float*        Cf;
};

// ---------------------------------------------------------------------------
// mma.sync fp16 GEMM, 2-term split: C = (Ahi+Alo) * fp16(B).
// C[128 x 128] per CTA, 256 thr = 8 warps (2m x 4n), warp tile 64x32.
// 2-stage cp.async pipeline, 2 CTAs/SM.
// EPI 0: fp32 out (ldc);  EPI 1: scatter [B,H,S,Hd] (split if Cl, else single)
// ---------------------------------------------------------------------------
template<int EPI>
__global__ void __launch_bounds__(256, 2)
tc_gemm(const __half* __restrict__ Ahi, const __half* __restrict__ Alo,
        GParams gpar, int K, int lda, int ldb, int ldc)
{
    extern __shared__ char dsm[];
    constexpr int ABYTES = 128 * 128;             // one A buffer: 128 rows x 64 fp16
    constexpr int BBYTES = 128 * 128;             // B hi: 128 rows x 64 fp16
    constexpr int STG    = 2 * ABYTES + BBYTES;   // 48 KB

    const int tid    = threadIdx.x;
    const int lane   = tid & 31;
    const int wid    = tid >> 5;
    const int warp_m = wid & 1;                   // 0..1
    const int warp_n = wid >> 1;                  // 0..3
    const int row0   = blockIdx.y * 128;
    const int col0   = blockIdx.x * 128;
    const int z      = blockIdx.z;

    const __half* __restrict__ Bh = gpar.Bh[z];
    const float* __restrict__ bias = gpar.bias[z];

    const uint32_t dyn0 = smem_u32(dsm);
    const uint32_t dyn  = (dyn0 + 1023) & ~1023u;

    const int nch = K / 64;

    auto load_chunk = [&](int c) {
        const uint32_t s = dyn + (c & 1) * STG;
        const int koff = c * 64;
        #pragma unroll
        for (int i = 0; i < 4; i++) {
            int lin = tid + i * 256;
            int r = lin >> 3, sg = lin & 7;
            uint32_t sw = sw128((uint32_t)(r * 128 + sg * 16));
            long long go = (long long)(row0 + r) * lda + koff + sg * 8;
            CPA16(s + sw,          (const void*)(Ahi + go));
            CPA16(s + ABYTES + sw, (const void*)(Alo + go));
        }
        #pragma unroll
        for (int i = 0; i < 4; i++) {
            int lin = tid + i * 256;
            int r = lin >> 3, sg = lin & 7;
            uint32_t sw = sw128((uint32_t)(r * 128 + sg * 16));
            long long go = (long long)(col0 + r) * ldb + koff + sg * 8;
            CPA16(s + 2 * ABYTES + sw, (const void*)(Bh + go));
        }
        CPA_COMMIT();
    };

    float acc[4][4][4];
    #pragma unroll
    for (int i = 0; i < 4; i++)
        #pragma unroll
        for (int j = 0; j < 4; j++)
            #pragma unroll
            for (int q = 0; q < 4; q++) acc[i][j][q] = 0.f;

    load_chunk(0);

    for (int c = 0; c < nch; c++) {
        if (c + 1 < nch) { load_chunk(c + 1); CPA_WAIT(1); }
        else             { CPA_WAIT(0); }
        __syncthreads();

        const uint32_t ah_ = dyn + (c & 1) * STG;
        const uint32_t al_ = ah_ + ABYTES;
        const uint32_t bh_ = ah_ + 2 * ABYTES;

        #pragma unroll
        for (int ks = 0; ks < 4; ks++) {
            uint32_t bH0[4], bH1[4];
            {
                const int q = lane >> 3, rr = lane & 7;
                int nr0 = warp_n * 32      + ((q >> 1) << 3) + rr;
                int nr1 = warp_n * 32 + 16 + ((q >> 1) << 3) + rr;
                uint32_t bo0 = (uint32_t)(nr0 * 128 + (ks * 16 + (q & 1) * 8) * 2);
                uint32_t bo1 = (uint32_t)(nr1 * 128 + (ks * 16 + (q & 1) * 8) * 2);
                LDSM_X4(bH0, bh_ + sw128(bo0));
                LDSM_X4(bH1, bh_ + sw128(bo1));
            }
            uint32_t aH[4][4];
            #pragma unroll
            for (int im = 0; im < 4; im++) {
                int r = warp_m * 64 + im * 16 + (lane & 15);
                uint32_t boff = (uint32_t)(r * 128 + ks * 32 + (lane >> 4) * 16);
                LDSM_X4(aH[im], ah_ + sw128(boff));
            }
            #pragma unroll
            for (int im = 0; im < 4; im++) {
                MMA16816(acc[im][0], aH[im], bH0[0], bH0[1]);
                MMA16816(acc[im][1], aH[im], bH0[2], bH0[3]);
                MMA16816(acc[im][2], aH[im], bH1[0], bH1[1]);
                MMA16816(acc[im][3], aH[im], bH1[2], bH1[3]);
            }
            // reuse aH registers for the lo fragments
            #pragma unroll
            for (int im = 0; im < 4; im++) {
                int r = warp_m * 64 + im * 16 + (lane & 15);
                uint32_t boff = (uint32_t)(r * 128 + ks * 32 + (lane >> 4) * 16);
                LDSM_X4(aH[im], al_ + sw128(boff));
            }
            #pragma unroll
            for (int im = 0; im < 4; im++) {
                MMA16816(acc[im][0], aH[im], bH0[0], bH0[1]);
                MMA16816(acc[im][1], aH[im], bH0[2], bH0[3]);
                MMA16816(acc[im][2], aH[im], bH1[0], bH1[1]);
                MMA16816(acc[im][3], aH[im], bH1[2], bH1[3]);
            }
        }
        __syncthreads();
    }

    const int g = lane >> 2, t = lane & 3;
    #pragma unroll
    for (int im = 0; im < 4; im++) {
        #pragma unroll
        for (int in = 0; in < 4; in++) {
            const float* ac = acc[im][in];
            const int n0 = col0 + warp_n * 32 + in * 8 + t * 2;
            #pragma unroll
            for (int half_ = 0; half_ < 2; half_++) {
                const int m = row0 + warp_m * 64 + im * 16 + g + half_ * 8;
                float v0 = ac[half_ * 2]     + bias[n0];
                float v1 = ac[half_ * 2 + 1] + bias[n0 + 1];
                if (EPI == 0) {
                    *(float2*)(gpar.Cf + (long long)m * ldc + n0) = make_float2(v0, v1);
                } else {
                    int b = m >> 10, s = m & 1023, h = n0 >> 6, d = n0 & 63;
                    long long off = ((((long long)(b * NHEAD + h) << 10) + s) * HDIM) + d;
                    if (gpar.Cl[z]) {
                        split_store_h(gpar.Ch[z], gpar.Cl[z], off, v0, v1);
                    } else {
                        __half2 H; H.x = __float2half_rn(v0); H.y = __float2half_rn(v1);
                        *(__half2*)(gpar.Ch[z] + off) = H;
                    }
                }
            }
        }
    }
}

// ---------------------------------------------------------------------------
// Fused flash attention, fp16 2-term: S = (Qh+Ql)*Kh, O += (Ph+Pl)*Vh.
// 2-stage KV pipeline (16 KB/stage), 2 CTAs/SM.
// ---------------------------------------------------------------------------
__global__ void __launch_bounds__(256, 2)
flash_attn(const __half* __restrict__ qh, const __half* __restrict__ ql,
           const __half* __restrict__ kh, const __half* __restrict__ vh,
           __half* __restrict__ wah, __half* __restrict__ wal)
{
    extern __shared__ char dsm[];
    const int tid  = threadIdx.x;
    const int lane = tid & 31;
    const int wid  = tid >> 5;
    const int z    = blockIdx.x;
    const int qrow0 = blockIdx.y * 128;

    const uint32_t dyn0 = smem_u32(dsm);
    const uint32_t dyn  = (dyn0 + 1023) & ~1023u;
    const uint32_t sQh = dyn, sQl = dyn + 16384;
    const uint32_t kvb = dyn + 32768;         // + (c&1)*16384 : Kh(8K), Vh(8K)

    const long long zoff = (long long)z * SEQ * HDIM;
    const __half* Qh = qh + zoff;
    const __half* Ql = ql + zoff;
    const __half* Kh = kh + zoff;
    const __half* Vh = vh + zoff;

    #pragma unroll
    for (int i = 0; i < 4; i++) {
        int lin = tid + i * 256;
        int r = lin >> 3, sg = lin & 7;
        uint32_t sw = sw128((uint32_t)(r * 128 + sg * 16));
        CPA16(sQh + sw, (const void*)(Qh + (long long)(qrow0 + r) * HDIM + sg * 8));
        CPA16(sQl + sw, (const void*)(Ql + (long long)(qrow0 + r) * HDIM + sg * 8));
    }
    CPA_COMMIT();

    auto load_kv = [&](int c) {
        uint32_t b = kvb + (c & 1) * 16384;
        int kv0 = c * 64;
        #pragma unroll
        for (int i = 0; i < 2; i++) {
            int lin = tid + i * 256;
            int r = lin >> 3, sg = lin & 7;
            uint32_t sw = sw128((uint32_t)(r * 128 + sg * 16));
            long long go = (long long)(kv0 + r) * HDIM + sg * 8;
            CPA16(b +        sw, (const void*)(Kh + go));
            CPA16(b + 8192 + sw, (const void*)(Vh + go));
        }
        CPA_COMMIT();
    };
    load_kv(0);

    const int g = lane >> 2, t = lane & 3;
    float O[8][4];
    #pragma unroll
    for (int j = 0; j < 8; j++)
        #pragma unroll
        for (int q = 0; q < 4; q++) O[j][q] = 0.f;
    float m0 = -1e30f, m1 = -1e30f, l0 = 0.f, l1 = 0.f;

    const int NKV = SEQ / 64;
    for (int c = 0; c < NKV; c++) {
        if (c + 1 < NKV) { load_kv(c + 1); CPA_WAIT(1); }
        else             { CPA_WAIT(0); }
        __syncthreads();

        const uint32_t base = kvb + (c & 1) * 16384;
        const uint32_t bKh = base, bVh = base + 8192;

        float S[8][4];
        #pragma unroll
        for (int j = 0; j < 8; j++)
            #pragma unroll
            for (int q = 0; q < 4; q++) S[j][q] = 0.f;

        // ---- S = (Qh+Ql) Kh^T ----
        #pragma unroll
        for (int ks = 0; ks < 4; ks++) {
            uint32_t aH[4], aL[4];
            {
                int r = wid * 16 + (lane & 15);
                uint32_t boff = (uint32_t)(r * 128 + ks * 32 + (lane >> 4) * 16);
                LDSM_X4(aH, sQh + sw128(boff));
                LDSM_X4(aL, sQl + sw128(boff));
            }
            #pragma unroll
            for (int gp = 0; gp < 2; gp++) {
                uint32_t bH0[4], bH1[4];
                const int q = lane >> 3, rr = lane & 7;
                int nr0 = (2 * gp)     * 16 + ((q >> 1) << 3) + rr;
                int nr1 = (2 * gp + 1) * 16 + ((q >> 1) << 3) + rr;
                uint32_t bo0 = (uint32_t)(nr0 * 128 + (ks * 16 + (q & 1) * 8) * 2);
                uint32_t bo1 = (uint32_t)(nr1 * 128 + (ks * 16 + (q & 1) * 8) * 2);
                LDSM_X4(bH0, bKh + sw128(bo0));
                LDSM_X4(bH1, bKh + sw128(bo1));
                float* S0 = S[4 * gp];     float* S1 = S[4 * gp + 1];
                float* S2 = S[4 * gp + 2]; float* S3 = S[4 * gp + 3];
                MMA16816(S0, aH, bH0[0], bH0[1]);
                MMA16816(S1, aH, bH0[2], bH0[3]);
                MMA16816(S2, aH, bH1[0], bH1[1]);
                MMA16816(S3, aH, bH1[2], bH1[3]);
                MMA16816(S0, aL, bH0[0], bH0[1]);
                MMA16816(S1, aL, bH0[2], bH0[3]);
                MMA16816(S2, aL, bH1[0], bH1[1]);
                MMA16816(S3, aL, bH1[2], bH1[3]);
            }
        }

        // ---- online softmax ----
        float mx0 = -1e30f, mx1 = -1e30f;
        #pragma unroll
        for (int j = 0; j < 8; j++) {
            S[j][0] *= 0.125f; S[j][1] *= 0.125f; S[j][2] *= 0.125f; S[j][3] *= 0.125f;
            mx0 = fmaxf(mx0, fmaxf(S[j][0], S[j][1]));
            mx1 = fmaxf(mx1, fmaxf(S[j][2], S[j][3]));
        }
        mx0 = fmaxf(mx0, __shfl_xor_sync(0xffffffffu, mx0, 1));
        mx0 = fmaxf(mx0, __shfl_xor_sync(0xffffffffu, mx0, 2));
        mx1 = fmaxf(mx1, __shfl_xor_sync(0xffffffffu, mx1, 1));
        mx1 = fmaxf(mx1, __shfl_xor_sync(0xffffffffu, mx1, 2));
        float nm0 = fmaxf(m0, mx0), nm1 = fmaxf(m1, mx1);
        float c0 = __expf(m0 - nm0), c1 = __expf(m1 - nm1);
        m0 = nm0; m1 = nm1;

        uint32_t PH[4][4], PL[4][4];
        float s0 = 0.f, s1 = 0.f;
        #pragma unroll
        for (int ck = 0; ck < 4; ck++) {
            float p00 = __expf(S[2 * ck][0] - nm0),   p01 = __expf(S[2 * ck][1] - nm0);
            float p02 = __expf(S[2 * ck][2] - nm1),   p03 = __expf(S[2 * ck][3] - nm1);
            float p10 = __expf(S[2 * ck + 1][0] - nm0), p11 = __expf(S[2 * ck + 1][1] - nm0);
            float p12 = __expf(S[2 * ck + 1][2] - nm1), p13 = __expf(S[2 * ck + 1][3] - nm1);
            s0 += p00 + p01 + p10 + p11;
            s1 += p02 + p03 + p12 + p13;
            pack_split_h(p00, p01, PH[ck][0], PL[ck][0]);
            pack_split_h(p02, p03, PH[ck][1], PL[ck][1]);
            pack_split_h(p10, p11, PH[ck][2], PL[ck][2]);
            pack_split_h(p12, p13, PH[ck][3], PL[ck][3]);
        }
        l0 = l0 * c0 + s0;
        l1 = l1 * c1 + s1;
        #pragma unroll
        for (int j = 0; j < 8; j++) {
            O[j][0] *= c0; O[j][1] *= c0; O[j][2] *= c1; O[j][3] *= c1;
        }

        // ---- O += (Ph+Pl) Vh ----
        #pragma unroll
        for (int ck = 0; ck < 4; ck++) {
            #pragma unroll
            for (int dp = 0; dp < 2; dp++) {
                uint32_t bH0[4], bH1[4];
                const int q = lane >> 3, rr = lane & 7;
                int kr = ck * 16 + (q & 1) * 8 + rr;
                int nc0 = (2 * dp)     * 16 + ((q >> 1) << 3);
                int nc1 = (2 * dp + 1) * 16 + ((q >> 1) << 3);
                uint32_t bo0 = (uint32_t)(kr * 128 + nc0 * 2);
                uint32_t bo1 = (uint32_t)(kr * 128 + nc1 * 2);
                LDSM_X4T(bH0, bVh + sw128(bo0));
                LDSM_X4T(bH1, bVh + sw128(bo1));
                float* O0 = O[4 * dp];     float* O1 = O[4 * dp + 1];
                float* O2 = O[4 * dp + 2]; float* O3 = O[4 * dp + 3];
                MMA16816(O0, PH[ck], bH0[0], bH0[1]);
                MMA16816(O1, PH[ck], bH0[2], bH0[3]);
                MMA16816(O2, PH[ck], bH1[0], bH1[1]);
                MMA16816(O3, PH[ck], bH1[2], bH1[3]);
                MMA16816(O0, PL[ck], bH0[0], bH0[1]);
                MMA16816(O1, PL[ck], bH0[2], bH0[3]);
                MMA16816(O2, PL[ck], bH1[0], bH1[1]);
                MMA16816(O3, PL[ck], bH1[2], bH1[3]);
            }
        }
        __syncthreads();
    }

    l0 += __shfl_xor_sync(0xffffffffu, l0, 1);
    l0 += __shfl_xor_sync(0xffffffffu, l0, 2);
    l1 += __shfl_xor_sync(0xffffffffu, l1, 1);
    l1 += __shfl_xor_sync(0xffffffffu, l1, 2);
    float inv0 = 1.f / l0, inv1 = 1.f / l1;

    const int b = z >> 4, h = z & 15;
    const int r0 = qrow0 + wid * 16 + g;
    #pragma unroll
    for (int j = 0; j < 8; j++) {
        int d = j * 8 + t * 2;
        long long off0 = (((long long)(b << 10) + r0) << 10) + h * HDIM + d;
        long long off1 = (((long long)(b << 10) + r0 + 8) << 10) + h * HDIM + d;
        split_store_h(wah, wal, off0, O[j][0] * inv0, O[j][1] * inv0);
        split_store_h(wah, wal, off1, O[j][2] * inv1, O[j][3] * inv1);
    }
}

// ---------------------------------------------------------------------------
// merged fp32 -> fp16 conversion: region 0 (x) hi/lo, regions 1..4 (W) hi only
// ---------------------------------------------------------------------------
struct SplitP {
    const float* in[5];
    __half* hi[5];
    __half* lo;          // only for region 0
};

__global__ void __launch_bounds__(256)
split_all(SplitP p)
{
    int idx = blockIdx.x * 256 + threadIdx.x;
    int r, local;
    if (idx < (1 << 20)) { r = 0; local = idx; }
    else {
        int t2 = idx - (1 << 20);
        r = 1 + (t2 >> 18);
        local = t2 & ((1 << 18) - 1);
    }
    float4 v = ((const float4*)p.in[r])[local];
    __half h0 = __float2half_rn(v.x), h1 = __float2half_rn(v.y);
    __half h2 = __float2half_rn(v.z), h3 = __float2half_rn(v.w);
    __half2 H0; H0.x = h0; H0.y = h1;
    __half2 H1; H1.x = h2; H1.y = h3;
    ((__half2*)p.hi[r])[2 * local]     = H0;
    ((__half2*)p.hi[r])[2 * local + 1] = H1;
    if (r == 0) {
        __half2 L0, L1;
        L0.x = __float2half_rn(v.x - __half2float(h0));
        L0.y = __float2half_rn(v.y - __half2float(h1));
        L1.x = __float2half_rn(v.z - __half2float(h2));
        L1.y = __float2half_rn(v.w - __half2float(h3));
        ((__half2*)p.lo)[2 * local]     = L0;
        ((__half2*)p.lo)[2 * local + 1] = L1;
    }
}

// ---------------------------------------------------------------------------
extern "C" void kernel_launch(void* const* d_in, const int* in_sizes, int n_in,
                              void* d_out, int out_size)
{
    (void)in_sizes; (void)n_in; (void)out_size;
    const float* x  = (const float*)d_in[0];
    const float* Wq = (const float*)d_in[1];
    const float* bq = (const float*)d_in[2];
    const float* Wk = (const float*)d_in[3];
    const float* bk = (const float*)d_in[4];
    const float* Wv = (const float*)d_in[5];
    const float* bv = (const float*)d_in[6];
    const float* Wp = (const float*)d_in[7];
    const float* bp = (const float*)d_in[8];
    float* out = (float*)d_out;

    __half *xh, *xl, *wh, *qh, *ql, *kh, *vh, *wah, *wal;
    cudaGetSymbolAddress((void**)&xh,  g_xh);
    cudaGetSymbolAddress((void**)&xl,  g_xl);
    cudaGetSymbolAddress((void**)&wh,  g_wh);
    cudaGetSymbolAddress((void**)&qh,  g_qh);
    cudaGetSymbolAddress((void**)&ql,  g_ql);
    cudaGetSymbolAddress((void**)&kh,  g_kh);
    cudaGetSymbolAddress((void**)&vh,  g_vh);
    cudaGetSymbolAddress((void**)&wah, g_wah);
    cudaGetSymbolAddress((void**)&wal, g_wal);

    const int SMGM = 2 * (2 * 16384 + 16384) + 1024;  // 99328 (2 CTAs/SM)
    const int SMFA = 32768 + 2 * 16384 + 1024;        // 66560 (2 CTAs/SM)
    cudaFuncSetAttribute(tc_gemm<1>, cudaFuncAttributeMaxDynamicSharedMemorySize, SMGM);
    cudaFuncSetAttribute(tc_gemm<0>, cudaFuncAttributeMaxDynamicSharedMemorySize, SMGM);
    cudaFuncSetAttribute(flash_attn, cudaFuncAttributeMaxDynamicSharedMemorySize, SMFA);

    SplitP sp;
    sp.in[0] = x;  sp.hi[0] = xh;  sp.lo = xl;
    sp.in[1] = Wq; sp.hi[1] = wh + 0 * DIM * DIM;
    sp.in[2] = Wk; sp.hi[2] = wh + 1 * DIM * DIM;
    sp.in[3] = Wv; sp.hi[3] = wh + 2 * DIM * DIM;
    sp.in[4] = Wp; sp.hi[4] = wh + 3 * DIM * DIM;
    split_all<<<(1 << 20) / 256 + 4 * ((1 << 18) / 256), 256>>>(sp);

    // QKV projections (z selects weight set): Q split, K/V single
    GParams gq = {};
    gq.Bh[0] = wh + 0 * DIM * DIM; gq.bias[0] = bq;
    gq.Bh[1] = wh + 1 * DIM * DIM; gq.bias[1] = bk;
    gq.Bh[2] = wh + 2 * DIM * DIM; gq.bias[2] = bv;
    gq.Ch[0] = qh; gq.Cl[0] = ql;
    gq.Ch[1] = kh; gq.Cl[1] = nullptr;
    gq.Ch[2] = vh; gq.Cl[2] = nullptr;
    dim3 gp(DIM / 128, NTOK / 128, 3);
    tc_gemm<1><<<gp, 256, SMGM>>>(xh, xl, gq, DIM, DIM, DIM, 0);

    dim3 gf(NBH, SEQ / 128);
    flash_attn<<<gf, 256, SMFA>>>(qh, ql, kh, vh, wah, wal);

    GParams go = {};
    go.Bh[0] = wh + 3 * DIM * DIM; go.bias[0] = bp;
    go.Cf = out;
    dim3 gop(DIM / 128, NTOK / 128, 1);
    tc_gemm<0><<<gop, 256, SMGM>>>(wah, wal, go, DIM, DIM, DIM, DIM);
}

// round 10
// speedup vs baseline: 2.4518x; 1.6120x over previous
#include <cuda_runtime.h>
#include <cuda_fp16.h>
#include <cstdint>
#include <math.h>

#define SEQ   1024
#define DIM   1024
#define NHEAD 16
#define HDIM  64
#define BATCH 4
#define NTOK  (BATCH*SEQ)
#define NBH   (BATCH*NHEAD)

// ---------------- scratch (allocation-free rule) ----------------
__device__ __half g_xh[NTOK*DIM];                 // x fp16
__device__ __half g_wh[4*DIM*DIM];                // weights fp16
__device__ __half g_qh[NBH*SEQ*HDIM];             // Q [bh,s,d]
__device__ __half g_kh[NBH*SEQ*HDIM];             // K
__device__ __half g_vh[NBH*SEQ*HDIM];             // V
__device__ __half g_wah[NTOK*DIM];                // wa [B,S,D]

// ---------------- PTX helpers ----------------
__device__ __forceinline__ uint32_t smem_u32(const void* p) {
    uint32_t a;
    asm("{ .reg .u64 t; cvta.to.shared.u64 t, %1; cvt.u32.u64 %0, t; }" : "=r"(a) : "l"(p));
    return a;
}
#define CPA16(d, s)  asm volatile("cp.async.cg.shared.global [%0], [%1], 16;" :: "r"(d), "l"(s) : "memory")
#define CPA_COMMIT() asm volatile("cp.async.commit_group;" ::: "memory")
#define CPA_WAIT(n)  asm volatile("cp.async.wait_group %0;" :: "n"(n) : "memory")

#define LDSM_X4(r, addr) \
    asm volatile("ldmatrix.sync.aligned.m8n8.x4.shared.b16 {%0,%1,%2,%3}, [%4];" \
        : "=r"((r)[0]), "=r"((r)[1]), "=r"((r)[2]), "=r"((r)[3]) : "r"(addr))
#define LDSM_X4T(r, addr) \
    asm volatile("ldmatrix.sync.aligned.m8n8.x4.trans.shared.b16 {%0,%1,%2,%3}, [%4];" \
        : "=r"((r)[0]), "=r"((r)[1]), "=r"((r)[2]), "=r"((r)[3]) : "r"(addr))

#define MMA16816(d, a, b0, b1) \
    asm volatile("mma.sync.aligned.m16n8k16.row.col.f32.f16.f16.f32 " \
        "{%0,%1,%2,%3}, {%4,%5,%6,%7}, {%8,%9}, {%0,%1,%2,%3};" \
        : "+f"((d)[0]), "+f"((d)[1]), "+f"((d)[2]), "+f"((d)[3]) \
        : "r"((a)[0]), "r"((a)[1]), "r"((a)[2]), "r"((a)[3]), "r"(b0), "r"(b1))

__device__ __forceinline__ uint32_t sw128(uint32_t boff) {
    return boff ^ ((boff >> 3) & 0x70);
}
__device__ __forceinline__ void pack_h2(float a, float b, uint32_t& h) {
    __half2 H; H.x = __float2half_rn(a); H.y = __float2half_rn(b);
    h = *(uint32_t*)&H;
}

struct GParams {
    const __half* Bh[3];
    const float*  bias[3];
    __half*       Ch[3];
    float*        Cf;
};

// ---------------------------------------------------------------------------
// mma.sync fp16 GEMM: C = A * B^T (+bias).
// C[128 x 128] per CTA, 256 thr = 8 warps (2m x 4n), warp tile 64x32.
// 2-stage cp.async pipeline, 2 CTAs/SM.
// EPI 0: fp32 out (ldc);  EPI 1: fp16 scatter [B,H,S,Hd]
// ---------------------------------------------------------------------------
template<int EPI>
__global__ void __launch_bounds__(256, 2)
tc_gemm(const __half* __restrict__ Ah, GParams gpar, int K, int lda, int ldb, int ldc)
{
    extern __shared__ char dsm[];
    constexpr int ABYTES = 128 * 128;        // 128 rows x 64 fp16
    constexpr int BBYTES = 128 * 128;
    constexpr int STG    = ABYTES + BBYTES;  // 32 KB

    const int tid    = threadIdx.x;
    const int lane   = tid & 31;
    const int wid    = tid >> 5;
    const int warp_m = wid & 1;
    const int warp_n = wid >> 1;
    const int row0   = blockIdx.y * 128;
    const int col0   = blockIdx.x * 128;
    const int z      = blockIdx.z;

    const __half* __restrict__ Bh  = gpar.Bh[z];
    const float* __restrict__ bias = gpar.bias[z];

    const uint32_t dyn0 = smem_u32(dsm);
    const uint32_t dyn  = (dyn0 + 1023) & ~1023u;

    const int nch = K / 64;

    auto load_chunk = [&](int c) {
        const uint32_t s = dyn + (c & 1) * STG;
        const int koff = c * 64;
        #pragma unroll
        for (int i = 0; i < 4; i++) {
            int lin = tid + i * 256;
            int r = lin >> 3, sg = lin & 7;
            uint32_t sw = sw128((uint32_t)(r * 128 + sg * 16));
            CPA16(s + sw, (const void*)(Ah + (long long)(row0 + r) * lda + koff + sg * 8));
        }
        #pragma unroll
        for (int i = 0; i < 4; i++) {
            int lin = tid + i * 256;
            int r = lin >> 3, sg = lin & 7;
            uint32_t sw = sw128((uint32_t)(r * 128 + sg * 16));
            CPA16(s + ABYTES + sw, (const void*)(Bh + (long long)(col0 + r) * ldb + koff + sg * 8));
        }
        CPA_COMMIT();
    };

    float acc[4][4][4];
    #pragma unroll
    for (int i = 0; i < 4; i++)
        #pragma unroll
        for (int j = 0; j < 4; j++)
            #pragma unroll
            for (int q = 0; q < 4; q++) acc[i][j][q] = 0.f;

    load_chunk(0);

    for (int c = 0; c < nch; c++) {
        if (c + 1 < nch) { load_chunk(c + 1); CPA_WAIT(1); }
        else             { CPA_WAIT(0); }
        __syncthreads();

        const uint32_t ah_ = dyn + (c & 1) * STG;
        const uint32_t bh_ = ah_ + ABYTES;

        #pragma unroll
        for (int ks = 0; ks < 4; ks++) {
            uint32_t bH0[4], bH1[4];
            {
                const int q = lane >> 3, rr = lane & 7;
                int nr0 = warp_n * 32      + ((q >> 1) << 3) + rr;
                int nr1 = warp_n * 32 + 16 + ((q >> 1) << 3) + rr;
                uint32_t bo0 = (uint32_t)(nr0 * 128 + (ks * 16 + (q & 1) * 8) * 2);
                uint32_t bo1 = (uint32_t)(nr1 * 128 + (ks * 16 + (q & 1) * 8) * 2);
                LDSM_X4(bH0, bh_ + sw128(bo0));
                LDSM_X4(bH1, bh_ + sw128(bo1));
            }
            uint32_t aH[4][4];
            #pragma unroll
            for (int im = 0; im < 4; im++) {
                int r = warp_m * 64 + im * 16 + (lane & 15);
                uint32_t boff = (uint32_t)(r * 128 + ks * 32 + (lane >> 4) * 16);
                LDSM_X4(aH[im], ah_ + sw128(boff));
            }
            #pragma unroll
            for (int im = 0; im < 4; im++) {
                MMA16816(acc[im][0], aH[im], bH0[0], bH0[1]);
                MMA16816(acc[im][1], aH[im], bH0[2], bH0[3]);
                MMA16816(acc[im][2], aH[im], bH1[0], bH1[1]);
                MMA16816(acc[im][3], aH[im], bH1[2], bH1[3]);
            }
        }
        __syncthreads();
    }

    const int g = lane >> 2, t = lane & 3;
    #pragma unroll
    for (int im = 0; im < 4; im++) {
        #pragma unroll
        for (int in = 0; in < 4; in++) {
            const float* ac = acc[im][in];
            const int n0 = col0 + warp_n * 32 + in * 8 + t * 2;
            #pragma unroll
            for (int half_ = 0; half_ < 2; half_++) {
                const int m = row0 + warp_m * 64 + im * 16 + g + half_ * 8;
                float v0 = ac[half_ * 2]     + bias[n0];
                float v1 = ac[half_ * 2 + 1] + bias[n0 + 1];
                if (EPI == 0) {
                    *(float2*)(gpar.Cf + (long long)m * ldc + n0) = make_float2(v0, v1);
                } else {
                    int b = m >> 10, s = m & 1023, h = n0 >> 6, d = n0 & 63;
                    long long off = ((((long long)(b * NHEAD + h) << 10) + s) * HDIM) + d;
                    __half2 H; H.x = __float2half_rn(v0); H.y = __float2half_rn(v1);
                    *(__half2*)(gpar.Ch[z] + off) = H;
                }
            }
        }
    }
}

// ---------------------------------------------------------------------------
// Fused flash attention, pure fp16 operands, fp32 accum/softmax.
// 2-stage KV pipeline (16 KB/stage), 2 CTAs/SM.
// ---------------------------------------------------------------------------
__global__ void __launch_bounds__(256, 2)
flash_attn(const __half* __restrict__ qh, const __half* __restrict__ kh,
           const __half* __restrict__ vh, __half* __restrict__ wah)
{
    extern __shared__ char dsm[];
    const int tid  = threadIdx.x;
    const int lane = tid & 31;
    const int wid  = tid >> 5;
    const int z    = blockIdx.x;
    const int qrow0 = blockIdx.y * 128;

    const uint32_t dyn0 = smem_u32(dsm);
    const uint32_t dyn  = (dyn0 + 1023) & ~1023u;
    const uint32_t sQh = dyn;
    const uint32_t kvb = dyn + 16384;       // + (c&1)*16384 : Kh(8K), Vh(8K)

    const long long zoff = (long long)z * SEQ * HDIM;
    const __half* Qh = qh + zoff;
    const __half* Kh = kh + zoff;
    const __half* Vh = vh + zoff;

    #pragma unroll
    for (int i = 0; i < 4; i++) {
        int lin = tid + i * 256;
        int r = lin >> 3, sg = lin & 7;
        uint32_t sw = sw128((uint32_t)(r * 128 + sg * 16));
        CPA16(sQh + sw, (const void*)(Qh + (long long)(qrow0 + r) * HDIM + sg * 8));
    }
    CPA_COMMIT();

    auto load_kv = [&](int c) {
        uint32_t b = kvb + (c & 1) * 16384;
        int kv0 = c * 64;
        #pragma unroll
        for (int i = 0; i < 2; i++) {
            int lin = tid + i * 256;
            int r = lin >> 3, sg = lin & 7;
            uint32_t sw = sw128((uint32_t)(r * 128 + sg * 16));
            long long go = (long long)(kv0 + r) * HDIM + sg * 8;
            CPA16(b +        sw, (const void*)(Kh + go));
            CPA16(b + 8192 + sw, (const void*)(Vh + go));
        }
        CPA_COMMIT();
    };
    load_kv(0);

    const int g = lane >> 2, t = lane & 3;
    float O[8][4];
    #pragma unroll
    for (int j = 0; j < 8; j++)
        #pragma unroll
        for (int q = 0; q < 4; q++) O[j][q] = 0.f;
    float m0 = -1e30f, m1 = -1e30f, l0 = 0.f, l1 = 0.f;

    const int NKV = SEQ / 64;
    for (int c = 0; c < NKV; c++) {
        if (c + 1 < NKV) { load_kv(c + 1); CPA_WAIT(1); }
        else             { CPA_WAIT(0); }
        __syncthreads();

        const uint32_t base = kvb + (c & 1) * 16384;
        const uint32_t bKh = base, bVh = base + 8192;

        float S[8][4];
        #pragma unroll
        for (int j = 0; j < 8; j++)
            #pragma unroll
            for (int q = 0; q < 4; q++) S[j][q] = 0.f;

        // ---- S = Q K^T ----
        #pragma unroll
        for (int ks = 0; ks < 4; ks++) {
            uint32_t aH[4];
            {
                int r = wid * 16 + (lane & 15);
                uint32_t boff = (uint32_t)(r * 128 + ks * 32 + (lane >> 4) * 16);
                LDSM_X4(aH, sQh + sw128(boff));
            }
            #pragma unroll
            for (int gp = 0; gp < 2; gp++) {
                uint32_t bH0[4], bH1[4];
                const int q = lane >> 3, rr = lane & 7;
                int nr0 = (2 * gp)     * 16 + ((q >> 1) << 3) + rr;
                int nr1 = (2 * gp + 1) * 16 + ((q >> 1) << 3) + rr;
                uint32_t bo0 = (uint32_t)(nr0 * 128 + (ks * 16 + (q & 1) * 8) * 2);
                uint32_t bo1 = (uint32_t)(nr1 * 128 + (ks * 16 + (q & 1) * 8) * 2);
                LDSM_X4(bH0, bKh + sw128(bo0));
                LDSM_X4(bH1, bKh + sw128(bo1));
                MMA16816(S[4 * gp],     aH, bH0[0], bH0[1]);
                MMA16816(S[4 * gp + 1], aH, bH0[2], bH0[3]);
                MMA16816(S[4 * gp + 2], aH, bH1[0], bH1[1]);
                MMA16816(S[4 * gp + 3], aH, bH1[2], bH1[3]);
            }
        }

        // ---- online softmax ----
        float mx0 = -1e30f, mx1 = -1e30f;
        #pragma unroll
        for (int j = 0; j < 8; j++) {
            S[j][0] *= 0.125f; S[j][1] *= 0.125f; S[j][2] *= 0.125f; S[j][3] *= 0.125f;
            mx0 = fmaxf(mx0, fmaxf(S[j][0], S[j][1]));
            mx1 = fmaxf(mx1, fmaxf(S[j][2], S[j][3]));
        }
        mx0 = fmaxf(mx0, __shfl_xor_sync(0xffffffffu, mx0, 1));
        mx0 = fmaxf(mx0, __shfl_xor_sync(0xffffffffu, mx0, 2));
        mx1 = fmaxf(mx1, __shfl_xor_sync(0xffffffffu, mx1, 1));
        mx1 = fmaxf(mx1, __shfl_xor_sync(0xffffffffu, mx1, 2));
        float nm0 = fmaxf(m0, mx0), nm1 = fmaxf(m1, mx1);
        float c0 = __expf(m0 - nm0), c1 = __expf(m1 - nm1);
        m0 = nm0; m1 = nm1;

        uint32_t PH[4][4];
        float s0 = 0.f, s1 = 0.f;
        #pragma unroll
        for (int ck = 0; ck < 4; ck++) {
            float p00 = __expf(S[2 * ck][0] - nm0),   p01 = __expf(S[2 * ck][1] - nm0);
            float p02 = __expf(S[2 * ck][2] - nm1),   p03 = __expf(S[2 * ck][3] - nm1);
            float p10 = __expf(S[2 * ck + 1][0] - nm0), p11 = __expf(S[2 * ck + 1][1] - nm0);
            float p12 = __expf(S[2 * ck + 1][2] - nm1), p13 = __expf(S[2 * ck + 1][3] - nm1);
            s0 += p00 + p01 + p10 + p11;
            s1 += p02 + p03 + p12 + p13;
            pack_h2(p00, p01, PH[ck][0]);
            pack_h2(p02, p03, PH[ck][1]);
            pack_h2(p10, p11, PH[ck][2]);
            pack_h2(p12, p13, PH[ck][3]);
        }
        l0 = l0 * c0 + s0;
        l1 = l1 * c1 + s1;
        #pragma unroll
        for (int j = 0; j < 8; j++) {
            O[j][0] *= c0; O[j][1] *= c0; O[j][2] *= c1; O[j][3] *= c1;
        }

        // ---- O += P V ----
        #pragma unroll
        for (int ck = 0; ck < 4; ck++) {
            #pragma unroll
            for (int dp = 0; dp < 2; dp++) {
                uint32_t bH0[4], bH1[4];
                const int q = lane >> 3, rr = lane & 7;
                int kr = ck * 16 + (q & 1) * 8 + rr;
                int nc0 = (2 * dp)     * 16 + ((q >> 1) << 3);
                int nc1 = (2 * dp + 1) * 16 + ((q >> 1) << 3);
                uint32_t bo0 = (uint32_t)(kr * 128 + nc0 * 2);
                uint32_t bo1 = (uint32_t)(kr * 128 + nc1 * 2);
                LDSM_X4T(bH0, bVh + sw128(bo0));
                LDSM_X4T(bH1, bVh + sw128(bo1));
                MMA16816(O[4 * dp],     PH[ck], bH0[0], bH0[1]);
                MMA16816(O[4 * dp + 1], PH[ck], bH0[2], bH0[3]);
                MMA16816(O[4 * dp + 2], PH[ck], bH1[0], bH1[1]);
                MMA16816(O[4 * dp + 3], PH[ck], bH1[2], bH1[3]);
            }
        }
        __syncthreads();
    }

    l0 += __shfl_xor_sync(0xffffffffu, l0, 1);
    l0 += __shfl_xor_sync(0xffffffffu, l0, 2);
    l1 += __shfl_xor_sync(0xffffffffu, l1, 1);
    l1 += __shfl_xor_sync(0xffffffffu, l1, 2);
    float inv0 = 1.f / l0, inv1 = 1.f / l1;

    const int b = z >> 4, h = z & 15;
    const int r0 = qrow0 + wid * 16 + g;
    #pragma unroll
    for (int j = 0; j < 8; j++) {
        int d = j * 8 + t * 2;
        long long off0 = (((long long)(b << 10) + r0) << 10) + h * HDIM + d;
        long long off1 = (((long long)(b << 10) + r0 + 8) << 10) + h * HDIM + d;
        __half2 H0; H0.x = __float2half_rn(O[j][0] * inv0); H0.y = __float2half_rn(O[j][1] * inv0);
        __half2 H1; H1.x = __float2half_rn(O[j][2] * inv1); H1.y = __float2half_rn(O[j][3] * inv1);
        *(__half2*)(wah + off0) = H0;
        *(__half2*)(wah + off1) = H1;
    }
}

// ---------------------------------------------------------------------------
// merged fp32 -> fp16 conversion for x + 4 weight matrices
// ---------------------------------------------------------------------------
struct SplitP {
    const float* in[5];
    __half* hi[5];
};

__global__ void __launch_bounds__(256)
split_all(SplitP p)
{
    int idx = blockIdx.x * 256 + threadIdx.x;
    int r, local;
    if (idx < (1 << 20)) { r = 0; local = idx; }
    else {
        int t2 = idx - (1 << 20);
        r = 1 + (t2 >> 18);
        local = t2 & ((1 << 18) - 1);
    }
    float4 v = ((const float4*)p.in[r])[local];
    __half2 H0; H0.x = __float2half_rn(v.x); H0.y = __float2half_rn(v.y);
    __half2 H1; H1.x = __float2half_rn(v.z); H1.y = __float2half_rn(v.w);
    ((__half2*)p.hi[r])[2 * local]     = H0;
    ((__half2*)p.hi[r])[2 * local + 1] = H1;
}

// ---------------------------------------------------------------------------
extern "C" void kernel_launch(void* const* d_in, const int* in_sizes, int n_in,
                              void* d_out, int out_size)
{
    (void)in_sizes; (void)n_in; (void)out_size;
    const float* x  = (const float*)d_in[0];
    const float* Wq = (const float*)d_in[1];
    const float* bq = (const float*)d_in[2];
    const float* Wk = (const float*)d_in[3];
    const float* bk = (const float*)d_in[4];
    const float* Wv = (const float*)d_in[5];
    const float* bv = (const float*)d_in[6];
    const float* Wp = (const float*)d_in[7];
    const float* bp = (const float*)d_in[8];
    float* out = (float*)d_out;

    __half *xh, *wh, *qh, *kh, *vh, *wah;
    cudaGetSymbolAddress((void**)&xh,  g_xh);
    cudaGetSymbolAddress((void**)&wh,  g_wh);
    cudaGetSymbolAddress((void**)&qh,  g_qh);
    cudaGetSymbolAddress((void**)&kh,  g_kh);
    cudaGetSymbolAddress((void**)&vh,  g_vh);
    cudaGetSymbolAddress((void**)&wah, g_wah);

    const int SMGM = 2 * 32768 + 1024;             // 66560 (2 CTAs/SM)
    const int SMFA = 16384 + 2 * 16384 + 1024;     // 50176 (2 CTAs/SM)
    cudaFuncSetAttribute(tc_gemm<1>, cudaFuncAttributeMaxDynamicSharedMemorySize, SMGM);
    cudaFuncSetAttribute(tc_gemm<0>, cudaFuncAttributeMaxDynamicSharedMemorySize, SMGM);
    cudaFuncSetAttribute(flash_attn, cudaFuncAttributeMaxDynamicSharedMemorySize, SMFA);

    SplitP sp;
    sp.in[0] = x;  sp.hi[0] = xh;
    sp.in[1] = Wq; sp.hi[1] = wh + 0 * DIM * DIM;
    sp.in[2] = Wk; sp.hi[2] = wh + 1 * DIM * DIM;
    sp.in[3] = Wv; sp.hi[3] = wh + 2 * DIM * DIM;
    sp.in[4] = Wp; sp.hi[4] = wh + 3 * DIM * DIM;
    split_all<<<(1 << 20) / 256 + 4 * ((1 << 18) / 256), 256>>>(sp);

    // QKV projections (z selects weight set) -> fp16 [B,H,S,Hd]
    GParams gq = {};
    gq.Bh[0] = wh + 0 * DIM * DIM; gq.bias[0] = bq; gq.Ch[0] = qh;
    gq.Bh[1] = wh + 1 * DIM * DIM; gq.bias[1] = bk; gq.Ch[1] = kh;
    gq.Bh[2] = wh + 2 * DIM * DIM; gq.bias[2] = bv; gq.Ch[2] = vh;
    dim3 gp(DIM / 128, NTOK / 128, 3);
    tc_gemm<1><<<gp, 256, SMGM>>>(xh, gq, DIM, DIM, DIM, 0);

    dim3 gf(NBH, SEQ / 128);
    flash_attn<<<gf, 256, SMFA>>>(qh, kh, vh, wah);

    GParams go = {};
    go.Bh[0] = wh + 3 * DIM * DIM; go.bias[0] = bp; go.Cf = out;
    dim3 gop(DIM / 128, NTOK / 128, 1);
    tc_gemm<0><<<gop, 256, SMGM>>>(wah, go, DIM, DIM, DIM, DIM);
}